// round 1
// baseline (speedup 1.0000x reference)
#include <cuda_runtime.h>
#include <math.h>

// Problem constants
#define BB 2
#define TT 2048
#define CC 1024
#define HH 16
#define HS 64
#define NROWS (BB*TT)        // 4096
#define LN_EPS 1e-5f

// ---------------------------------------------------------------------------
// Scratch (static __device__ arrays -- no allocation allowed)
// ---------------------------------------------------------------------------
__device__ float g_h   [NROWS*CC];        // LN1 output
__device__ float g_wqkv[CC*3*CC];         // packed [C, 3C] qkv weight
__device__ float g_bqkv[3*CC];            // packed qkv bias
__device__ float g_qkv [NROWS*3*CC];      // q|k|v activations
__device__ float g_attn[NROWS*CC];        // attention output (head-concat)
__device__ float g_x1  [NROWS*CC];        // after attn residual
__device__ float g_h2  [NROWS*CC];        // LN2 output
__device__ float g_ff  [NROWS*4*CC];      // FF hidden

// ---------------------------------------------------------------------------
// Pack Wq/Wk/Wv [H,C,HS] -> g_wqkv [C, 3C] (col = w*1024 + h*64 + d), biases too
// ---------------------------------------------------------------------------
__global__ void pack_qkv_kernel(const float* __restrict__ Wq,
                                const float* __restrict__ Wk,
                                const float* __restrict__ Wv,
                                const float* __restrict__ bq,
                                const float* __restrict__ bk,
                                const float* __restrict__ bv) {
    int e = blockIdx.x * blockDim.x + threadIdx.x;   // over H*C*HS = 1,048,576
    if (e < HH*CC*HS) {
        int d = e % HS;
        int c = (e / HS) % CC;
        int h = e / (HS*CC);
        int col = h*HS + d;
        g_wqkv[(size_t)c*3*CC +        col] = Wq[e];
        g_wqkv[(size_t)c*3*CC + CC   + col] = Wk[e];
        g_wqkv[(size_t)c*3*CC + 2*CC + col] = Wv[e];
    }
    if (e < CC) {
        g_bqkv[e]        = bq[e];
        g_bqkv[CC + e]   = bk[e];
        g_bqkv[2*CC + e] = bv[e];
    }
}

// ---------------------------------------------------------------------------
// LayerNorm over axis=1 (sequence axis!): stats over t for each (b, c).
// unbiased var (ddof=1), eps OUTSIDE sqrt.
// grid: (CC/8, BB), block: (8, 32)
// ---------------------------------------------------------------------------
__global__ void ln_seq_kernel(const float* __restrict__ x,
                              const float* __restrict__ gamma,
                              const float* __restrict__ beta,
                              float* __restrict__ out) {
    int b  = blockIdx.y;
    int tx = threadIdx.x, ty = threadIdx.y;
    int c  = blockIdx.x * 8 + tx;
    const float* xp = x   + (size_t)b*TT*CC + c;
    float*       op = out + (size_t)b*TT*CC + c;

    float s = 0.f, sq = 0.f;
    for (int t = ty; t < TT; t += 32) {
        float v = xp[(size_t)t*CC];
        s += v; sq += v*v;
    }
    __shared__ float ssum[32][8];
    __shared__ float ssq [32][8];
    ssum[ty][tx] = s; ssq[ty][tx] = sq;
    __syncthreads();
    for (int off = 16; off > 0; off >>= 1) {
        if (ty < off) {
            ssum[ty][tx] += ssum[ty+off][tx];
            ssq [ty][tx] += ssq [ty+off][tx];
        }
        __syncthreads();
    }
    __shared__ float meanv[8], rstdv[8];
    if (ty == 0) {
        float mean = ssum[0][tx] * (1.0f / TT);
        float var  = (ssq[0][tx] - (float)TT * mean * mean) * (1.0f / (TT - 1));
        meanv[tx]  = mean;
        rstdv[tx]  = 1.0f / (sqrtf(var) + LN_EPS);
    }
    __syncthreads();
    float mean = meanv[tx], rstd = rstdv[tx];
    float g = gamma[c], bt = beta[c];
    for (int t = ty; t < TT; t += 32) {
        float v = xp[(size_t)t*CC];
        op[(size_t)t*CC] = g * ((v - mean) * rstd) + bt;
    }
}

// ---------------------------------------------------------------------------
// Generic fp32 tiled GEMM: C[M,N] = A[M,K] @ B[K,N] (+bias, +relu, +residual)
// BM=BN=128, BK=16, 256 threads, 8x8 microtile. All dims multiples of 128/16.
// ---------------------------------------------------------------------------
template<int DOBIAS, int DORELU, int DORES>
__global__ void __launch_bounds__(256)
gemm128_kernel(const float* __restrict__ A, const float* __restrict__ Bm,
               const float* __restrict__ bias, const float* __restrict__ res,
               float* __restrict__ Cm, int M, int N, int K) {
    __shared__ float As[16][132];   // k-major, transposed A tile
    __shared__ float Bs[16][132];

    int tx = threadIdx.x, ty = threadIdx.y;
    int tid = ty*16 + tx;
    int m0 = blockIdx.y * 128, n0 = blockIdx.x * 128;

    float acc[8][8];
#pragma unroll
    for (int i = 0; i < 8; i++)
#pragma unroll
        for (int j = 0; j < 8; j++) acc[i][j] = 0.f;

    int arow  = tid >> 2;      // 0..63
    int acol4 = tid & 3;       // 0..3   (k offset /4)
    int brow  = tid >> 5;      // 0..7
    int bcol4 = tid & 31;      // 0..31  (n offset /4)

    for (int k0 = 0; k0 < K; k0 += 16) {
#pragma unroll
        for (int p = 0; p < 2; p++) {
            int r = arow + p*64;
            float4 v = *(const float4*)&A[(size_t)(m0+r)*K + k0 + acol4*4];
            As[acol4*4+0][r] = v.x;
            As[acol4*4+1][r] = v.y;
            As[acol4*4+2][r] = v.z;
            As[acol4*4+3][r] = v.w;
        }
#pragma unroll
        for (int p = 0; p < 2; p++) {
            int r = brow + p*8;
            float4 v = *(const float4*)&Bm[(size_t)(k0+r)*N + n0 + bcol4*4];
            *(float4*)&Bs[r][bcol4*4] = v;
        }
        __syncthreads();
#pragma unroll
        for (int k = 0; k < 16; k++) {
            float4 a0 = *(const float4*)&As[k][ty*4];
            float4 a1 = *(const float4*)&As[k][64 + ty*4];
            float4 b0 = *(const float4*)&Bs[k][tx*4];
            float4 b1 = *(const float4*)&Bs[k][64 + tx*4];
            float av[8] = {a0.x,a0.y,a0.z,a0.w,a1.x,a1.y,a1.z,a1.w};
            float bv[8] = {b0.x,b0.y,b0.z,b0.w,b1.x,b1.y,b1.z,b1.w};
#pragma unroll
            for (int i = 0; i < 8; i++)
#pragma unroll
                for (int j = 0; j < 8; j++)
                    acc[i][j] += av[i]*bv[j];
        }
        __syncthreads();
    }

#pragma unroll
    for (int i = 0; i < 8; i++) {
        int m = m0 + ((i < 4) ? (ty*4 + i) : (64 + ty*4 + (i-4)));
#pragma unroll
        for (int j = 0; j < 8; j++) {
            int n = n0 + ((j < 4) ? (tx*4 + j) : (64 + tx*4 + (j-4)));
            float v = acc[i][j];
            if (DOBIAS) v += bias[n];
            if (DORELU) v = fmaxf(v, 0.f);
            if (DORES)  v += res[(size_t)m*N + n];
            Cm[(size_t)m*N + n] = v;
        }
    }
}

// ---------------------------------------------------------------------------
// Flash-style attention (non-causal, full softmax over all T keys).
// grid: (T/64, H, B), block (16,16). q-tile = 64 rows, kv-tile = 64.
// Reads q/k/v from g_qkv [4096, 3072]; writes head-concat to g_attn [4096,1024].
// Dynamic smem: QsT[64][68] + KVs[64][68] + Ps[64][68] = 52224 B
// ---------------------------------------------------------------------------
#define ATTN_SMEM (3*64*68*4)

__global__ void __launch_bounds__(256) attn_kernel() {
    extern __shared__ float sm[];
    float* QsT = sm;                 // [k][r]  stride 68
    float* KVs = sm + 64*68;         // K: [k][c] transposed; then V: [s][d] natural
    float* Ps  = sm + 2*64*68;       // [c][r]  stride 68

    int tx = threadIdx.x, ty = threadIdx.y;
    int tid = ty*16 + tx;
    int b = blockIdx.z, h = blockIdx.y;
    int tq0 = blockIdx.x * 64;

    const float* qbase = g_qkv + (size_t)b*TT*3*CC + (size_t)h*HS;
    const float* kbase = qbase + CC;
    const float* vbase = qbase + 2*CC;

    // load Q tile transposed: QsT[k][r]
#pragma unroll
    for (int p = 0; p < 4; p++) {
        int idx = tid + p*256;
        int r = idx >> 4, c4 = idx & 15;
        float4 v = *(const float4*)&qbase[(size_t)(tq0 + r)*3*CC + c4*4];
        QsT[(c4*4+0)*68 + r] = v.x;
        QsT[(c4*4+1)*68 + r] = v.y;
        QsT[(c4*4+2)*68 + r] = v.z;
        QsT[(c4*4+3)*68 + r] = v.w;
    }

    float O[16];
#pragma unroll
    for (int i = 0; i < 16; i++) O[i] = 0.f;
    float mrow[4], lrow[4];
#pragma unroll
    for (int i = 0; i < 4; i++) { mrow[i] = -1e30f; lrow[i] = 0.f; }

    __syncthreads();

    for (int kt = 0; kt < TT; kt += 64) {
        // load K tile transposed: KVs[k][c]
#pragma unroll
        for (int p = 0; p < 4; p++) {
            int idx = tid + p*256;
            int r = idx >> 4, c4 = idx & 15;
            float4 v = *(const float4*)&kbase[(size_t)(kt + r)*3*CC + c4*4];
            KVs[(c4*4+0)*68 + r] = v.x;
            KVs[(c4*4+1)*68 + r] = v.y;
            KVs[(c4*4+2)*68 + r] = v.z;
            KVs[(c4*4+3)*68 + r] = v.w;
        }
        __syncthreads();

        // S = Q K^T : S[i][j] for rows ty*4+i, cols tx*4+j
        float S[4][4];
#pragma unroll
        for (int i = 0; i < 4; i++)
#pragma unroll
            for (int j = 0; j < 4; j++) S[i][j] = 0.f;

#pragma unroll 8
        for (int k = 0; k < 64; k++) {
            float4 qa = *(const float4*)(QsT + k*68 + ty*4);
            float4 kb = *(const float4*)(KVs + k*68 + tx*4);
            float qv[4] = {qa.x,qa.y,qa.z,qa.w};
            float kv[4] = {kb.x,kb.y,kb.z,kb.w};
#pragma unroll
            for (int i = 0; i < 4; i++)
#pragma unroll
                for (int j = 0; j < 4; j++)
                    S[i][j] += qv[i]*kv[j];
        }
        __syncthreads();   // K reads done before KVs is reused for V

        // online softmax update (per row, reduced across the 16 tx lanes)
        const float scale = 0.125f;   // HS^-0.5
#pragma unroll
        for (int i = 0; i < 4; i++) {
            float mx = -1e30f;
#pragma unroll
            for (int j = 0; j < 4; j++) { S[i][j] *= scale; mx = fmaxf(mx, S[i][j]); }
#pragma unroll
            for (int off = 8; off > 0; off >>= 1)
                mx = fmaxf(mx, __shfl_xor_sync(0xffffffffu, mx, off));
            float mnew = fmaxf(mrow[i], mx);
            float rs = 0.f;
#pragma unroll
            for (int j = 0; j < 4; j++) {
                float pexp = __expf(S[i][j] - mnew);
                S[i][j] = pexp; rs += pexp;
            }
#pragma unroll
            for (int off = 8; off > 0; off >>= 1)
                rs += __shfl_xor_sync(0xffffffffu, rs, off);
            float alpha = __expf(mrow[i] - mnew);
            lrow[i] = lrow[i]*alpha + rs;
            mrow[i] = mnew;
#pragma unroll
            for (int j = 0; j < 4; j++) O[i*4+j] *= alpha;
        }

        // store P transposed: Ps[c][r]
#pragma unroll
        for (int j = 0; j < 4; j++) {
            float4 pv = make_float4(S[0][j], S[1][j], S[2][j], S[3][j]);
            *(float4*)(Ps + (tx*4+j)*68 + ty*4) = pv;
        }

        // load V tile natural: KVs[s][d]
#pragma unroll
        for (int p = 0; p < 4; p++) {
            int idx = tid + p*256;
            int r = idx >> 4, c4 = idx & 15;
            float4 v = *(const float4*)&vbase[(size_t)(kt + r)*3*CC + c4*4];
            *(float4*)(KVs + r*68 + c4*4) = v;
        }
        __syncthreads();

        // O += P V
#pragma unroll 8
        for (int s = 0; s < 64; s++) {
            float4 pa = *(const float4*)(Ps  + s*68 + ty*4);
            float4 vb = *(const float4*)(KVs + s*68 + tx*4);
            float pv[4] = {pa.x,pa.y,pa.z,pa.w};
            float vv[4] = {vb.x,vb.y,vb.z,vb.w};
#pragma unroll
            for (int i = 0; i < 4; i++)
#pragma unroll
                for (int j = 0; j < 4; j++)
                    O[i*4+j] += pv[i]*vv[j];
        }
        __syncthreads();   // Ps/KVs reads done before next iteration overwrites
    }

    // finalize + write head-concat layout [b,t, h*64+d]
#pragma unroll
    for (int i = 0; i < 4; i++) {
        float inv_l = 1.0f / lrow[i];
        int row = b*TT + tq0 + ty*4 + i;
        float4 o4 = make_float4(O[i*4+0]*inv_l, O[i*4+1]*inv_l,
                                O[i*4+2]*inv_l, O[i*4+3]*inv_l);
        *(float4*)&g_attn[(size_t)row*CC + h*HS + tx*4] = o4;
    }
}

// ---------------------------------------------------------------------------
// Launch
// ---------------------------------------------------------------------------
extern "C" void kernel_launch(void* const* d_in, const int* in_sizes, int n_in,
                              void* d_out, int out_size) {
    const float* x      = (const float*)d_in[0];
    const float* Wq     = (const float*)d_in[1];
    const float* bq     = (const float*)d_in[2];
    const float* Wk     = (const float*)d_in[3];
    const float* bk     = (const float*)d_in[4];
    const float* Wv     = (const float*)d_in[5];
    const float* bv     = (const float*)d_in[6];
    const float* Wo     = (const float*)d_in[7];
    const float* bo     = (const float*)d_in[8];
    const float* W1     = (const float*)d_in[9];
    const float* b1     = (const float*)d_in[10];
    const float* W2     = (const float*)d_in[11];
    const float* b2     = (const float*)d_in[12];
    const float* gamma1 = (const float*)d_in[13];
    const float* beta1  = (const float*)d_in[14];
    const float* gamma2 = (const float*)d_in[15];
    const float* beta2  = (const float*)d_in[16];
    float* out = (float*)d_out;

    float *p_h, *p_wqkv, *p_bqkv, *p_qkv, *p_attn, *p_x1, *p_h2, *p_ff;
    cudaGetSymbolAddress((void**)&p_h,    g_h);
    cudaGetSymbolAddress((void**)&p_wqkv, g_wqkv);
    cudaGetSymbolAddress((void**)&p_bqkv, g_bqkv);
    cudaGetSymbolAddress((void**)&p_qkv,  g_qkv);
    cudaGetSymbolAddress((void**)&p_attn, g_attn);
    cudaGetSymbolAddress((void**)&p_x1,   g_x1);
    cudaGetSymbolAddress((void**)&p_h2,   g_h2);
    cudaGetSymbolAddress((void**)&p_ff,   g_ff);

    cudaFuncSetAttribute(attn_kernel,
                         cudaFuncAttributeMaxDynamicSharedMemorySize, ATTN_SMEM);

    dim3 tb(16, 16);

    // 0. pack qkv weights/biases
    pack_qkv_kernel<<<(HH*CC*HS + 255)/256, 256>>>(Wq, Wk, Wv, bq, bk, bv);

    // 1. LN1 (over sequence axis)
    ln_seq_kernel<<<dim3(CC/8, BB), dim3(8, 32)>>>(x, gamma1, beta1, p_h);

    // 2. QKV GEMM: [4096,1024] @ [1024,3072] + bias
    gemm128_kernel<1,0,0><<<dim3(3*CC/128, NROWS/128), tb>>>(
        p_h, p_wqkv, p_bqkv, nullptr, p_qkv, NROWS, 3*CC, CC);

    // 3. attention
    attn_kernel<<<dim3(TT/64, HH, BB), tb, ATTN_SMEM>>>();

    // 4. output projection + residual: x1 = x + attn @ Wo + bo
    gemm128_kernel<1,0,1><<<dim3(CC/128, NROWS/128), tb>>>(
        p_attn, Wo, bo, x, p_x1, NROWS, CC, CC);

    // 5. LN2
    ln_seq_kernel<<<dim3(CC/8, BB), dim3(8, 32)>>>(p_x1, gamma2, beta2, p_h2);

    // 6. FF1 + relu: [4096,1024] @ [1024,4096]
    gemm128_kernel<1,1,0><<<dim3(4*CC/128, NROWS/128), tb>>>(
        p_h2, W1, b1, nullptr, p_ff, NROWS, 4*CC, CC);

    // 7. FF2 + residual -> out: [4096,4096] @ [4096,1024]
    gemm128_kernel<1,0,1><<<dim3(CC/128, NROWS/128), tb>>>(
        p_ff, W2, b2, p_x1, out, NROWS, CC, 4*CC);
}

// round 3
// speedup vs baseline: 1.7829x; 1.7829x over previous
#include <cuda_runtime.h>
#include <math.h>
#include <stdint.h>

// Problem constants
#define BB 2
#define TT 2048
#define CC 1024
#define HH 16
#define HS 64
#define NROWS (BB*TT)        // 4096
#define LN_EPS 1e-5f

// ---------------------------------------------------------------------------
// Scratch (static __device__ arrays -- no allocation allowed)
// ---------------------------------------------------------------------------
__device__ float g_h   [NROWS*CC];        // LN1 output
__device__ float g_wqkv[CC*3*CC];         // packed [C, 3C] qkv weight
__device__ float g_bqkv[3*CC];            // packed qkv bias
__device__ float g_qkv [NROWS*3*CC];      // q|k|v activations
__device__ float g_attn[NROWS*CC];        // attention output (head-concat)
__device__ float g_x1  [NROWS*CC];        // after attn residual
__device__ float g_h2  [NROWS*CC];        // LN2 output
__device__ float g_ff  [NROWS*4*CC];      // FF hidden

__device__ __forceinline__ float to_tf32(float x) {
    uint32_t u;
    asm("cvt.rna.tf32.f32 %0, %1;" : "=r"(u) : "f"(x));
    return __uint_as_float(u);
}

// ---------------------------------------------------------------------------
// Pack Wq/Wk/Wv [H,C,HS] -> g_wqkv [C, 3C] (col = w*1024 + h*64 + d), biases too
// ---------------------------------------------------------------------------
__global__ void pack_qkv_kernel(const float* __restrict__ Wq,
                                const float* __restrict__ Wk,
                                const float* __restrict__ Wv,
                                const float* __restrict__ bq,
                                const float* __restrict__ bk,
                                const float* __restrict__ bv) {
    int e = blockIdx.x * blockDim.x + threadIdx.x;
    if (e < HH*CC*HS) {
        int d = e % HS;
        int c = (e / HS) % CC;
        int h = e / (HS*CC);
        int col = h*HS + d;
        g_wqkv[(size_t)c*3*CC +        col] = Wq[e];
        g_wqkv[(size_t)c*3*CC + CC   + col] = Wk[e];
        g_wqkv[(size_t)c*3*CC + 2*CC + col] = Wv[e];
    }
    if (e < CC) {
        g_bqkv[e]        = bq[e];
        g_bqkv[CC + e]   = bk[e];
        g_bqkv[2*CC + e] = bv[e];
    }
}

// ---------------------------------------------------------------------------
// LayerNorm over axis=1 (sequence axis!): stats over t for each (b, c).
// unbiased var (ddof=1), eps OUTSIDE sqrt.
// ---------------------------------------------------------------------------
__global__ void ln_seq_kernel(const float* __restrict__ x,
                              const float* __restrict__ gamma,
                              const float* __restrict__ beta,
                              float* __restrict__ out) {
    int b  = blockIdx.y;
    int tx = threadIdx.x, ty = threadIdx.y;
    int c  = blockIdx.x * 8 + tx;
    const float* xp = x   + (size_t)b*TT*CC + c;
    float*       op = out + (size_t)b*TT*CC + c;

    float s = 0.f, sq = 0.f;
    for (int t = ty; t < TT; t += 32) {
        float v = xp[(size_t)t*CC];
        s += v; sq += v*v;
    }
    __shared__ float ssum[32][8];
    __shared__ float ssq [32][8];
    ssum[ty][tx] = s; ssq[ty][tx] = sq;
    __syncthreads();
    for (int off = 16; off > 0; off >>= 1) {
        if (ty < off) {
            ssum[ty][tx] += ssum[ty+off][tx];
            ssq [ty][tx] += ssq [ty+off][tx];
        }
        __syncthreads();
    }
    __shared__ float meanv[8], rstdv[8];
    if (ty == 0) {
        float mean = ssum[0][tx] * (1.0f / TT);
        float var  = (ssq[0][tx] - (float)TT * mean * mean) * (1.0f / (TT - 1));
        meanv[tx]  = mean;
        rstdv[tx]  = 1.0f / (sqrtf(var) + LN_EPS);
    }
    __syncthreads();
    float mean = meanv[tx], rstd = rstdv[tx];
    float g = gamma[c], bt = beta[c];
    for (int t = ty; t < TT; t += 32) {
        float v = xp[(size_t)t*CC];
        op[(size_t)t*CC] = g * ((v - mean) * rstd) + bt;
    }
}

// ---------------------------------------------------------------------------
// TF32 tensor-core GEMM: C[M,N] = A[M,K] @ B[K,N] (+bias, +relu, +residual)
// Block tile 128x128, BK=32, 256 threads = 8 warps (4m x 2n), warp tile 32x64.
// mma.sync.aligned.m16n8k8.row.col.f32.tf32.tf32.f32
// ---------------------------------------------------------------------------
#define MMA_TF32(d, a, b)                                                     \
    asm volatile(                                                             \
        "mma.sync.aligned.m16n8k8.row.col.f32.tf32.tf32.f32 "                 \
        "{%0,%1,%2,%3},{%4,%5,%6,%7},{%8,%9},{%0,%1,%2,%3};\n"                \
        : "+f"((d)[0]), "+f"((d)[1]), "+f"((d)[2]), "+f"((d)[3])              \
        : "r"((a)[0]), "r"((a)[1]), "r"((a)[2]), "r"((a)[3]),                 \
          "r"((b)[0]), "r"((b)[1]))

template<int DOBIAS, int DORELU, int DORES>
__global__ void __launch_bounds__(256, 2)
gemm_tc_kernel(const float* __restrict__ A, const float* __restrict__ Bm,
               const float* __restrict__ bias, const float* __restrict__ res,
               float* __restrict__ Cm, int M, int N, int K) {
    __shared__ float As[128][36];    // row-major m x k (stride 36: banks 4r+c distinct)
    __shared__ float Bs[32][136];    // row-major k x n (stride 136: banks 8k+n distinct)

    int tid  = threadIdx.x;
    int lane = tid & 31, wid = tid >> 5;
    int wm = (wid >> 1) * 32;        // warp m offset within block
    int wn = (wid & 1) * 64;         // warp n offset within block
    int g  = lane >> 2;              // groupID
    int tg = lane & 3;               // thread-in-group
    int m0 = blockIdx.y * 128, n0 = blockIdx.x * 128;

    float acc[2][8][4];
#pragma unroll
    for (int mf = 0; mf < 2; mf++)
#pragma unroll
        for (int nf = 0; nf < 8; nf++)
#pragma unroll
            for (int r = 0; r < 4; r++) acc[mf][nf][r] = 0.f;

    int ar = tid >> 3, ac = (tid & 7) * 4;    // A staging: 4 rows-of-32 passes
    int br = tid >> 5, bc = (tid & 31) * 4;   // B staging: 4 rows-of-8 passes

    for (int k0 = 0; k0 < K; k0 += 32) {
#pragma unroll
        for (int p = 0; p < 4; p++) {                 // <-- FIX: full 128 rows
            float4 av = *(const float4*)&A[(size_t)(m0 + ar + 32*p)*K + k0 + ac];
            av.x = to_tf32(av.x); av.y = to_tf32(av.y);
            av.z = to_tf32(av.z); av.w = to_tf32(av.w);
            *(float4*)&As[ar + 32*p][ac] = av;
        }
#pragma unroll
        for (int p = 0; p < 4; p++) {
            float4 bv = *(const float4*)&Bm[(size_t)(k0 + br + 8*p)*N + n0 + bc];
            bv.x = to_tf32(bv.x); bv.y = to_tf32(bv.y);
            bv.z = to_tf32(bv.z); bv.w = to_tf32(bv.w);
            *(float4*)&Bs[br + 8*p][bc] = bv;
        }
        __syncthreads();

#pragma unroll
        for (int ks = 0; ks < 4; ks++) {
            int kk = ks * 8;
            uint32_t afr[2][4];
#pragma unroll
            for (int mf = 0; mf < 2; mf++) {
                int r = wm + mf*16 + g;
                afr[mf][0] = __float_as_uint(As[r    ][kk + tg    ]);
                afr[mf][1] = __float_as_uint(As[r + 8][kk + tg    ]);
                afr[mf][2] = __float_as_uint(As[r    ][kk + tg + 4]);
                afr[mf][3] = __float_as_uint(As[r + 8][kk + tg + 4]);
            }
#pragma unroll
            for (int nf = 0; nf < 8; nf++) {
                uint32_t bfr[2];
                bfr[0] = __float_as_uint(Bs[kk + tg    ][wn + nf*8 + g]);
                bfr[1] = __float_as_uint(Bs[kk + tg + 4][wn + nf*8 + g]);
#pragma unroll
                for (int mf = 0; mf < 2; mf++)
                    MMA_TF32(acc[mf][nf], afr[mf], bfr);
            }
        }
        __syncthreads();
    }

    // epilogue: c0,c1 -> row g, cols 2*tg, 2*tg+1 ; c2,c3 -> row g+8
#pragma unroll
    for (int mf = 0; mf < 2; mf++) {
#pragma unroll
        for (int nf = 0; nf < 8; nf++) {
            int r  = m0 + wm + mf*16 + g;
            int cb = n0 + wn + nf*8 + 2*tg;
            float2 v0 = make_float2(acc[mf][nf][0], acc[mf][nf][1]);
            float2 v1 = make_float2(acc[mf][nf][2], acc[mf][nf][3]);
            if (DOBIAS) {
                float2 bsv = *(const float2*)&bias[cb];
                v0.x += bsv.x; v0.y += bsv.y;
                v1.x += bsv.x; v1.y += bsv.y;
            }
            if (DORELU) {
                v0.x = fmaxf(v0.x, 0.f); v0.y = fmaxf(v0.y, 0.f);
                v1.x = fmaxf(v1.x, 0.f); v1.y = fmaxf(v1.y, 0.f);
            }
            if (DORES) {
                float2 r0 = *(const float2*)&res[(size_t)r*N + cb];
                float2 r1 = *(const float2*)&res[(size_t)(r+8)*N + cb];
                v0.x += r0.x; v0.y += r0.y;
                v1.x += r1.x; v1.y += r1.y;
            }
            *(float2*)&Cm[(size_t)r*N + cb]     = v0;
            *(float2*)&Cm[(size_t)(r+8)*N + cb] = v1;
        }
    }
}

// ---------------------------------------------------------------------------
// Flash-style attention (fp32 SIMT, verified in R1).
// ---------------------------------------------------------------------------
#define ATTN_SMEM (3*64*68*4)

__global__ void __launch_bounds__(256) attn_kernel() {
    extern __shared__ float sm[];
    float* QsT = sm;
    float* KVs = sm + 64*68;
    float* Ps  = sm + 2*64*68;

    int tx = threadIdx.x, ty = threadIdx.y;
    int tid = ty*16 + tx;
    int b = blockIdx.z, h = blockIdx.y;
    int tq0 = blockIdx.x * 64;

    const float* qbase = g_qkv + (size_t)b*TT*3*CC + (size_t)h*HS;
    const float* kbase = qbase + CC;
    const float* vbase = qbase + 2*CC;

#pragma unroll
    for (int p = 0; p < 4; p++) {
        int idx = tid + p*256;
        int r = idx >> 4, c4 = idx & 15;
        float4 v = *(const float4*)&qbase[(size_t)(tq0 + r)*3*CC + c4*4];
        QsT[(c4*4+0)*68 + r] = v.x;
        QsT[(c4*4+1)*68 + r] = v.y;
        QsT[(c4*4+2)*68 + r] = v.z;
        QsT[(c4*4+3)*68 + r] = v.w;
    }

    float O[16];
#pragma unroll
    for (int i = 0; i < 16; i++) O[i] = 0.f;
    float mrow[4], lrow[4];
#pragma unroll
    for (int i = 0; i < 4; i++) { mrow[i] = -1e30f; lrow[i] = 0.f; }

    __syncthreads();

    for (int kt = 0; kt < TT; kt += 64) {
#pragma unroll
        for (int p = 0; p < 4; p++) {
            int idx = tid + p*256;
            int r = idx >> 4, c4 = idx & 15;
            float4 v = *(const float4*)&kbase[(size_t)(kt + r)*3*CC + c4*4];
            KVs[(c4*4+0)*68 + r] = v.x;
            KVs[(c4*4+1)*68 + r] = v.y;
            KVs[(c4*4+2)*68 + r] = v.z;
            KVs[(c4*4+3)*68 + r] = v.w;
        }
        __syncthreads();

        float S[4][4];
#pragma unroll
        for (int i = 0; i < 4; i++)
#pragma unroll
            for (int j = 0; j < 4; j++) S[i][j] = 0.f;

#pragma unroll 8
        for (int k = 0; k < 64; k++) {
            float4 qa = *(const float4*)(QsT + k*68 + ty*4);
            float4 kb = *(const float4*)(KVs + k*68 + tx*4);
            float qv[4] = {qa.x,qa.y,qa.z,qa.w};
            float kv[4] = {kb.x,kb.y,kb.z,kb.w};
#pragma unroll
            for (int i = 0; i < 4; i++)
#pragma unroll
                for (int j = 0; j < 4; j++)
                    S[i][j] += qv[i]*kv[j];
        }
        __syncthreads();

        const float scale = 0.125f;
#pragma unroll
        for (int i = 0; i < 4; i++) {
            float mx = -1e30f;
#pragma unroll
            for (int j = 0; j < 4; j++) { S[i][j] *= scale; mx = fmaxf(mx, S[i][j]); }
#pragma unroll
            for (int off = 8; off > 0; off >>= 1)
                mx = fmaxf(mx, __shfl_xor_sync(0xffffffffu, mx, off));
            float mnew = fmaxf(mrow[i], mx);
            float rs = 0.f;
#pragma unroll
            for (int j = 0; j < 4; j++) {
                float pexp = __expf(S[i][j] - mnew);
                S[i][j] = pexp; rs += pexp;
            }
#pragma unroll
            for (int off = 8; off > 0; off >>= 1)
                rs += __shfl_xor_sync(0xffffffffu, rs, off);
            float alpha = __expf(mrow[i] - mnew);
            lrow[i] = lrow[i]*alpha + rs;
            mrow[i] = mnew;
#pragma unroll
            for (int j = 0; j < 4; j++) O[i*4+j] *= alpha;
        }

#pragma unroll
        for (int j = 0; j < 4; j++) {
            float4 pv = make_float4(S[0][j], S[1][j], S[2][j], S[3][j]);
            *(float4*)(Ps + (tx*4+j)*68 + ty*4) = pv;
        }

#pragma unroll
        for (int p = 0; p < 4; p++) {
            int idx = tid + p*256;
            int r = idx >> 4, c4 = idx & 15;
            float4 v = *(const float4*)&vbase[(size_t)(kt + r)*3*CC + c4*4];
            *(float4*)(KVs + r*68 + c4*4) = v;
        }
        __syncthreads();

#pragma unroll 8
        for (int s = 0; s < 64; s++) {
            float4 pa = *(const float4*)(Ps  + s*68 + ty*4);
            float4 vb = *(const float4*)(KVs + s*68 + tx*4);
            float pv[4] = {pa.x,pa.y,pa.z,pa.w};
            float vv[4] = {vb.x,vb.y,vb.z,vb.w};
#pragma unroll
            for (int i = 0; i < 4; i++)
#pragma unroll
                for (int j = 0; j < 4; j++)
                    O[i*4+j] += pv[i]*vv[j];
        }
        __syncthreads();
    }

#pragma unroll
    for (int i = 0; i < 4; i++) {
        float inv_l = 1.0f / lrow[i];
        int row = b*TT + tq0 + ty*4 + i;
        float4 o4 = make_float4(O[i*4+0]*inv_l, O[i*4+1]*inv_l,
                                O[i*4+2]*inv_l, O[i*4+3]*inv_l);
        *(float4*)&g_attn[(size_t)row*CC + h*HS + tx*4] = o4;
    }
}

// ---------------------------------------------------------------------------
// Launch
// ---------------------------------------------------------------------------
extern "C" void kernel_launch(void* const* d_in, const int* in_sizes, int n_in,
                              void* d_out, int out_size) {
    const float* x      = (const float*)d_in[0];
    const float* Wq     = (const float*)d_in[1];
    const float* bq     = (const float*)d_in[2];
    const float* Wk     = (const float*)d_in[3];
    const float* bk     = (const float*)d_in[4];
    const float* Wv     = (const float*)d_in[5];
    const float* bv     = (const float*)d_in[6];
    const float* Wo     = (const float*)d_in[7];
    const float* bo     = (const float*)d_in[8];
    const float* W1     = (const float*)d_in[9];
    const float* b1     = (const float*)d_in[10];
    const float* W2     = (const float*)d_in[11];
    const float* b2     = (const float*)d_in[12];
    const float* gamma1 = (const float*)d_in[13];
    const float* beta1  = (const float*)d_in[14];
    const float* gamma2 = (const float*)d_in[15];
    const float* beta2  = (const float*)d_in[16];
    float* out = (float*)d_out;

    float *p_h, *p_wqkv, *p_bqkv, *p_qkv, *p_attn, *p_x1, *p_h2, *p_ff;
    cudaGetSymbolAddress((void**)&p_h,    g_h);
    cudaGetSymbolAddress((void**)&p_wqkv, g_wqkv);
    cudaGetSymbolAddress((void**)&p_bqkv, g_bqkv);
    cudaGetSymbolAddress((void**)&p_qkv,  g_qkv);
    cudaGetSymbolAddress((void**)&p_attn, g_attn);
    cudaGetSymbolAddress((void**)&p_x1,   g_x1);
    cudaGetSymbolAddress((void**)&p_h2,   g_h2);
    cudaGetSymbolAddress((void**)&p_ff,   g_ff);

    cudaFuncSetAttribute(attn_kernel,
                         cudaFuncAttributeMaxDynamicSharedMemorySize, ATTN_SMEM);

    // 0. pack qkv weights/biases
    pack_qkv_kernel<<<(HH*CC*HS + 255)/256, 256>>>(Wq, Wk, Wv, bq, bk, bv);

    // 1. LN1 (over sequence axis)
    ln_seq_kernel<<<dim3(CC/8, BB), dim3(8, 32)>>>(x, gamma1, beta1, p_h);

    // 2. QKV GEMM: [4096,1024] @ [1024,3072] + bias
    gemm_tc_kernel<1,0,0><<<dim3(3*CC/128, NROWS/128), 256>>>(
        p_h, p_wqkv, p_bqkv, nullptr, p_qkv, NROWS, 3*CC, CC);

    // 3. attention
    attn_kernel<<<dim3(TT/64, HH, BB), dim3(16,16), ATTN_SMEM>>>();

    // 4. output projection + residual: x1 = x + attn @ Wo + bo
    gemm_tc_kernel<1,0,1><<<dim3(CC/128, NROWS/128), 256>>>(
        p_attn, Wo, bo, x, p_x1, NROWS, CC, CC);

    // 5. LN2
    ln_seq_kernel<<<dim3(CC/8, BB), dim3(8, 32)>>>(p_x1, gamma2, beta2, p_h2);

    // 6. FF1 + relu: [4096,1024] @ [1024,4096]
    gemm_tc_kernel<1,1,0><<<dim3(4*CC/128, NROWS/128), 256>>>(
        p_h2, W1, b1, nullptr, p_ff, NROWS, 4*CC, CC);

    // 7. FF2 + residual -> out: [4096,4096] @ [4096,1024]
    gemm_tc_kernel<1,0,1><<<dim3(CC/128, NROWS/128), 256>>>(
        p_ff, W2, b2, p_x1, out, NROWS, CC, 4*CC);
}

// round 4
// speedup vs baseline: 2.6664x; 1.4955x over previous
#include <cuda_runtime.h>
#include <math.h>
#include <stdint.h>

// Problem constants
#define BB 2
#define TT 2048
#define CC 1024
#define HH 16
#define HS 64
#define NROWS (BB*TT)        // 4096
#define LN_EPS 1e-5f

// ---------------------------------------------------------------------------
// Scratch (static __device__ arrays -- no allocation allowed)
// ---------------------------------------------------------------------------
__device__ float g_h   [NROWS*CC];        // LN1 output
__device__ float g_wqkv[CC*3*CC];         // packed [C, 3C] qkv weight
__device__ float g_bqkv[3*CC];            // packed qkv bias
__device__ float g_qkv [NROWS*3*CC];      // q|k|v activations
__device__ float g_attn[NROWS*CC];        // attention output (head-concat)
__device__ float g_x1  [NROWS*CC];        // after attn residual
__device__ float g_h2  [NROWS*CC];        // LN2 output
__device__ float g_ff  [NROWS*4*CC];      // FF hidden

__device__ __forceinline__ float to_tf32(float x) {
    uint32_t u;
    asm("cvt.rna.tf32.f32 %0, %1;" : "=r"(u) : "f"(x));
    return __uint_as_float(u);
}

// exp2 on the MUFU pipe (1 instruction)
__device__ __forceinline__ float ex2_mufu(float y) {
    float r;
    asm("ex2.approx.ftz.f32 %0, %1;" : "=f"(r) : "f"(y));
    return r;
}

// exp2 on the FMA pipe: magic-round split + deg-4 poly + exponent splice.
// valid for y in [-80, 80] (caller clamps); rel err ~4e-5.
__device__ __forceinline__ float ex2_poly(float y) {
    float r = y + 12582912.f;               // round-to-nearest-int via magic
    int   n = __float_as_int(r);            // low bits = integer part (biased)
    float t = r - 12582912.f;
    float f = y - t;                        // f in [-0.5, 0.5]
    float p = 0.00961813f;
    p = fmaf(p, f, 0.05550411f);
    p = fmaf(p, f, 0.24022651f);
    p = fmaf(p, f, 0.69314718f);
    p = fmaf(p, f, 1.0f);
    // (n<<23) == (k<<23) where k = integer part, since low 9 bits of the
    // magic's bit pattern are zero; splice into exponent of p.
    return __int_as_float(__float_as_int(p) + (n << 23));
}

// ---------------------------------------------------------------------------
// Pack Wq/Wk/Wv [H,C,HS] -> g_wqkv [C, 3C] (col = w*1024 + h*64 + d), biases too
// ---------------------------------------------------------------------------
__global__ void pack_qkv_kernel(const float* __restrict__ Wq,
                                const float* __restrict__ Wk,
                                const float* __restrict__ Wv,
                                const float* __restrict__ bq,
                                const float* __restrict__ bk,
                                const float* __restrict__ bv) {
    int e = blockIdx.x * blockDim.x + threadIdx.x;
    if (e < HH*CC*HS) {
        int d = e % HS;
        int c = (e / HS) % CC;
        int h = e / (HS*CC);
        int col = h*HS + d;
        g_wqkv[(size_t)c*3*CC +        col] = Wq[e];
        g_wqkv[(size_t)c*3*CC + CC   + col] = Wk[e];
        g_wqkv[(size_t)c*3*CC + 2*CC + col] = Wv[e];
    }
    if (e < CC) {
        g_bqkv[e]        = bq[e];
        g_bqkv[CC + e]   = bk[e];
        g_bqkv[2*CC + e] = bv[e];
    }
}

// ---------------------------------------------------------------------------
// LayerNorm over axis=1 (sequence axis!): stats over t for each (b, c).
// ---------------------------------------------------------------------------
__global__ void ln_seq_kernel(const float* __restrict__ x,
                              const float* __restrict__ gamma,
                              const float* __restrict__ beta,
                              float* __restrict__ out) {
    int b  = blockIdx.y;
    int tx = threadIdx.x, ty = threadIdx.y;
    int c  = blockIdx.x * 8 + tx;
    const float* xp = x   + (size_t)b*TT*CC + c;
    float*       op = out + (size_t)b*TT*CC + c;

    float s = 0.f, sq = 0.f;
    for (int t = ty; t < TT; t += 32) {
        float v = xp[(size_t)t*CC];
        s += v; sq += v*v;
    }
    __shared__ float ssum[32][8];
    __shared__ float ssq [32][8];
    ssum[ty][tx] = s; ssq[ty][tx] = sq;
    __syncthreads();
    for (int off = 16; off > 0; off >>= 1) {
        if (ty < off) {
            ssum[ty][tx] += ssum[ty+off][tx];
            ssq [ty][tx] += ssq [ty+off][tx];
        }
        __syncthreads();
    }
    __shared__ float meanv[8], rstdv[8];
    if (ty == 0) {
        float mean = ssum[0][tx] * (1.0f / TT);
        float var  = (ssq[0][tx] - (float)TT * mean * mean) * (1.0f / (TT - 1));
        meanv[tx]  = mean;
        rstdv[tx]  = 1.0f / (sqrtf(var) + LN_EPS);
    }
    __syncthreads();
    float mean = meanv[tx], rstd = rstdv[tx];
    float g = gamma[c], bt = beta[c];
    for (int t = ty; t < TT; t += 32) {
        float v = xp[(size_t)t*CC];
        op[(size_t)t*CC] = g * ((v - mean) * rstd) + bt;
    }
}

// ---------------------------------------------------------------------------
// TF32 tensor-core GEMM (verified R3): C = A@B (+bias, +relu, +residual)
// ---------------------------------------------------------------------------
#define MMA_TF32(d, a, b)                                                     \
    asm volatile(                                                             \
        "mma.sync.aligned.m16n8k8.row.col.f32.tf32.tf32.f32 "                 \
        "{%0,%1,%2,%3},{%4,%5,%6,%7},{%8,%9},{%0,%1,%2,%3};\n"                \
        : "+f"((d)[0]), "+f"((d)[1]), "+f"((d)[2]), "+f"((d)[3])              \
        : "r"((a)[0]), "r"((a)[1]), "r"((a)[2]), "r"((a)[3]),                 \
          "r"((b)[0]), "r"((b)[1]))

template<int DOBIAS, int DORELU, int DORES>
__global__ void __launch_bounds__(256, 2)
gemm_tc_kernel(const float* __restrict__ A, const float* __restrict__ Bm,
               const float* __restrict__ bias, const float* __restrict__ res,
               float* __restrict__ Cm, int M, int N, int K) {
    __shared__ float As[128][36];
    __shared__ float Bs[32][136];

    int tid  = threadIdx.x;
    int lane = tid & 31, wid = tid >> 5;
    int wm = (wid >> 1) * 32;
    int wn = (wid & 1) * 64;
    int g  = lane >> 2;
    int tg = lane & 3;
    int m0 = blockIdx.y * 128, n0 = blockIdx.x * 128;

    float acc[2][8][4];
#pragma unroll
    for (int mf = 0; mf < 2; mf++)
#pragma unroll
        for (int nf = 0; nf < 8; nf++)
#pragma unroll
            for (int r = 0; r < 4; r++) acc[mf][nf][r] = 0.f;

    int ar = tid >> 3, ac = (tid & 7) * 4;
    int br = tid >> 5, bc = (tid & 31) * 4;

    for (int k0 = 0; k0 < K; k0 += 32) {
#pragma unroll
        for (int p = 0; p < 4; p++) {
            float4 av = *(const float4*)&A[(size_t)(m0 + ar + 32*p)*K + k0 + ac];
            av.x = to_tf32(av.x); av.y = to_tf32(av.y);
            av.z = to_tf32(av.z); av.w = to_tf32(av.w);
            *(float4*)&As[ar + 32*p][ac] = av;
        }
#pragma unroll
        for (int p = 0; p < 4; p++) {
            float4 bv = *(const float4*)&Bm[(size_t)(k0 + br + 8*p)*N + n0 + bc];
            bv.x = to_tf32(bv.x); bv.y = to_tf32(bv.y);
            bv.z = to_tf32(bv.z); bv.w = to_tf32(bv.w);
            *(float4*)&Bs[br + 8*p][bc] = bv;
        }
        __syncthreads();

#pragma unroll
        for (int ks = 0; ks < 4; ks++) {
            int kk = ks * 8;
            uint32_t afr[2][4];
#pragma unroll
            for (int mf = 0; mf < 2; mf++) {
                int r = wm + mf*16 + g;
                afr[mf][0] = __float_as_uint(As[r    ][kk + tg    ]);
                afr[mf][1] = __float_as_uint(As[r + 8][kk + tg    ]);
                afr[mf][2] = __float_as_uint(As[r    ][kk + tg + 4]);
                afr[mf][3] = __float_as_uint(As[r + 8][kk + tg + 4]);
            }
#pragma unroll
            for (int nf = 0; nf < 8; nf++) {
                uint32_t bfr[2];
                bfr[0] = __float_as_uint(Bs[kk + tg    ][wn + nf*8 + g]);
                bfr[1] = __float_as_uint(Bs[kk + tg + 4][wn + nf*8 + g]);
#pragma unroll
                for (int mf = 0; mf < 2; mf++)
                    MMA_TF32(acc[mf][nf], afr[mf], bfr);
            }
        }
        __syncthreads();
    }

#pragma unroll
    for (int mf = 0; mf < 2; mf++) {
#pragma unroll
        for (int nf = 0; nf < 8; nf++) {
            int r  = m0 + wm + mf*16 + g;
            int cb = n0 + wn + nf*8 + 2*tg;
            float2 v0 = make_float2(acc[mf][nf][0], acc[mf][nf][1]);
            float2 v1 = make_float2(acc[mf][nf][2], acc[mf][nf][3]);
            if (DOBIAS) {
                float2 bsv = *(const float2*)&bias[cb];
                v0.x += bsv.x; v0.y += bsv.y;
                v1.x += bsv.x; v1.y += bsv.y;
            }
            if (DORELU) {
                v0.x = fmaxf(v0.x, 0.f); v0.y = fmaxf(v0.y, 0.f);
                v1.x = fmaxf(v1.x, 0.f); v1.y = fmaxf(v1.y, 0.f);
            }
            if (DORES) {
                float2 r0 = *(const float2*)&res[(size_t)r*N + cb];
                float2 r1 = *(const float2*)&res[(size_t)(r+8)*N + cb];
                v0.x += r0.x; v0.y += r0.y;
                v1.x += r1.x; v1.y += r1.y;
            }
            *(float2*)&Cm[(size_t)r*N + cb]     = v0;
            *(float2*)&Cm[(size_t)(r+8)*N + cb] = v1;
        }
    }
}

// ---------------------------------------------------------------------------
// Tensor-core flash attention, no-max softmax in base-2 domain.
// q-tile 128 rows, kv-tile 64, 8 warps; warp owns 16 q-rows x full width.
// S mma: A=Q (pre-scaled by 0.125*log2e), B=K.  Softmax sum via V ones-column.
// smem: Qs[128][68] Ks[64][68] Vs[64][72] Ps[128][68]  = 105472 B
// ---------------------------------------------------------------------------
#define QS_STRIDE 68
#define KS_STRIDE 68
#define VS_STRIDE 72
#define PS_STRIDE 68
#define SM_QS 0
#define SM_KS (128*QS_STRIDE)
#define SM_VS (SM_KS + 64*KS_STRIDE)
#define SM_PS (SM_VS + 64*VS_STRIDE)
#define ATTN_SMEM ((SM_PS + 128*PS_STRIDE)*4)
#define QSCALE 0.18033688f    /* 0.125 * log2(e) */

__global__ void __launch_bounds__(256, 2) attn_tc_kernel() {
    extern __shared__ float sm[];
    float* Qs = sm + SM_QS;
    float* Ks = sm + SM_KS;
    float* Vs = sm + SM_VS;
    float* Ps = sm + SM_PS;

    int tid = threadIdx.x, lane = tid & 31, wid = tid >> 5;
    int g = lane >> 2, tg = lane & 3;
    int b = blockIdx.z, h = blockIdx.y;
    int tq0 = blockIdx.x * 128;
    int wr = wid * 16;

    const float* qbase = g_qkv + (size_t)b*TT*3*CC + (size_t)h*HS;
    const float* kbase = qbase + CC;
    const float* vbase = qbase + 2*CC;

    // load Q tile (pre-scaled, tf32)
#pragma unroll
    for (int p = 0; p < 8; p++) {
        int idx = tid + p*256;
        int r = idx >> 4, c4 = idx & 15;
        float4 v = *(const float4*)&qbase[(size_t)(tq0 + r)*3*CC + c4*4];
        v.x = to_tf32(v.x * QSCALE); v.y = to_tf32(v.y * QSCALE);
        v.z = to_tf32(v.z * QSCALE); v.w = to_tf32(v.w * QSCALE);
        *(float4*)&Qs[r*QS_STRIDE + c4*4] = v;
    }
    // V ones-column block (cols 64..71): col 64 = 1, rest 0 (static)
#pragma unroll
    for (int p = 0; p < 2; p++) {
        int idx = tid + p*256;          // 0..511 = 64 rows x 8 cols
        int r = idx >> 3, c = idx & 7;
        Vs[r*VS_STRIDE + 64 + c] = (c == 0) ? 1.0f : 0.0f;
    }

    float o[9][4];
#pragma unroll
    for (int i = 0; i < 9; i++)
#pragma unroll
        for (int j = 0; j < 4; j++) o[i][j] = 0.f;

    __syncthreads();

    for (int kt = 0; kt < TT; kt += 64) {
        // load K and V tiles (tf32)
#pragma unroll
        for (int p = 0; p < 4; p++) {
            int idx = tid + p*256;
            int r = idx >> 4, c4 = idx & 15;
            float4 kv = *(const float4*)&kbase[(size_t)(kt + r)*3*CC + c4*4];
            kv.x = to_tf32(kv.x); kv.y = to_tf32(kv.y);
            kv.z = to_tf32(kv.z); kv.w = to_tf32(kv.w);
            *(float4*)&Ks[r*KS_STRIDE + c4*4] = kv;
            float4 vv = *(const float4*)&vbase[(size_t)(kt + r)*3*CC + c4*4];
            vv.x = to_tf32(vv.x); vv.y = to_tf32(vv.y);
            vv.z = to_tf32(vv.z); vv.w = to_tf32(vv.w);
            *(float4*)&Vs[r*VS_STRIDE + c4*4] = vv;
        }
        __syncthreads();

        // S = Q K^T (in log2 domain) -> exp2 -> P (streamed per 8-col frag)
#pragma unroll
        for (int nf = 0; nf < 8; nf++) {
            float s[4] = {0.f, 0.f, 0.f, 0.f};
#pragma unroll
            for (int k8 = 0; k8 < 8; k8++) {
                int kk = k8 * 8;
                uint32_t a[4], bb[2];
                a[0] = __float_as_uint(Qs[(wr+g  )*QS_STRIDE + kk + tg    ]);
                a[1] = __float_as_uint(Qs[(wr+g+8)*QS_STRIDE + kk + tg    ]);
                a[2] = __float_as_uint(Qs[(wr+g  )*QS_STRIDE + kk + tg + 4]);
                a[3] = __float_as_uint(Qs[(wr+g+8)*QS_STRIDE + kk + tg + 4]);
                bb[0] = __float_as_uint(Ks[(nf*8+g)*KS_STRIDE + kk + tg    ]);
                bb[1] = __float_as_uint(Ks[(nf*8+g)*KS_STRIDE + kk + tg + 4]);
                MMA_TF32(s, a, bb);
            }
            float p0, p1, p2, p3;
            if (nf < 3) {   // MUFU pipe (3/8 of work)
                p0 = ex2_mufu(fminf(s[0], 80.f));
                p1 = ex2_mufu(fminf(s[1], 80.f));
                p2 = ex2_mufu(fminf(s[2], 80.f));
                p3 = ex2_mufu(fminf(s[3], 80.f));
            } else {        // FMA pipe (5/8 of work)
                p0 = ex2_poly(fminf(fmaxf(s[0], -80.f), 80.f));
                p1 = ex2_poly(fminf(fmaxf(s[1], -80.f), 80.f));
                p2 = ex2_poly(fminf(fmaxf(s[2], -80.f), 80.f));
                p3 = ex2_poly(fminf(fmaxf(s[3], -80.f), 80.f));
            }
            float2 w0 = make_float2(to_tf32(p0), to_tf32(p1));
            float2 w1 = make_float2(to_tf32(p2), to_tf32(p3));
            *(float2*)&Ps[(wr+g  )*PS_STRIDE + nf*8 + 2*tg] = w0;
            *(float2*)&Ps[(wr+g+8)*PS_STRIDE + nf*8 + 2*tg] = w1;
        }
        __syncwarp();   // Ps rows are warp-private; order write->read in-warp

        // O += P V  (9th n-frag accumulates the row sums via ones column)
#pragma unroll
        for (int nf = 0; nf < 9; nf++) {
#pragma unroll
            for (int k8 = 0; k8 < 8; k8++) {
                int kk = k8 * 8;
                uint32_t a[4], bb[2];
                a[0] = __float_as_uint(Ps[(wr+g  )*PS_STRIDE + kk + tg    ]);
                a[1] = __float_as_uint(Ps[(wr+g+8)*PS_STRIDE + kk + tg    ]);
                a[2] = __float_as_uint(Ps[(wr+g  )*PS_STRIDE + kk + tg + 4]);
                a[3] = __float_as_uint(Ps[(wr+g+8)*PS_STRIDE + kk + tg + 4]);
                bb[0] = __float_as_uint(Vs[(kk+tg  )*VS_STRIDE + nf*8 + g]);
                bb[1] = __float_as_uint(Vs[(kk+tg+4)*VS_STRIDE + nf*8 + g]);
                MMA_TF32(o[nf], a, bb);
            }
        }
        __syncthreads();   // all reads done before next tile overwrites Ks/Vs
    }

    // finalize: l lives in o[8][0] (row g) / o[8][2] (row g+8) of tg==0 lanes
    float l0 = __shfl_sync(0xffffffffu, o[8][0], lane & ~3);
    float l1 = __shfl_sync(0xffffffffu, o[8][2], lane & ~3);
    float inv0 = 1.0f / l0, inv1 = 1.0f / l1;

    int row0 = b*TT + tq0 + wr + g;
#pragma unroll
    for (int nf = 0; nf < 8; nf++) {
        int col = h*HS + nf*8 + 2*tg;
        float2 v0 = make_float2(o[nf][0]*inv0, o[nf][1]*inv0);
        float2 v1 = make_float2(o[nf][2]*inv1, o[nf][3]*inv1);
        *(float2*)&g_attn[(size_t)row0*CC + col]     = v0;
        *(float2*)&g_attn[(size_t)(row0+8)*CC + col] = v1;
    }
}

// ---------------------------------------------------------------------------
// Launch
// ---------------------------------------------------------------------------
extern "C" void kernel_launch(void* const* d_in, const int* in_sizes, int n_in,
                              void* d_out, int out_size) {
    const float* x      = (const float*)d_in[0];
    const float* Wq     = (const float*)d_in[1];
    const float* bq     = (const float*)d_in[2];
    const float* Wk     = (const float*)d_in[3];
    const float* bk     = (const float*)d_in[4];
    const float* Wv     = (const float*)d_in[5];
    const float* bv     = (const float*)d_in[6];
    const float* Wo     = (const float*)d_in[7];
    const float* bo     = (const float*)d_in[8];
    const float* W1     = (const float*)d_in[9];
    const float* b1     = (const float*)d_in[10];
    const float* W2     = (const float*)d_in[11];
    const float* b2     = (const float*)d_in[12];
    const float* gamma1 = (const float*)d_in[13];
    const float* beta1  = (const float*)d_in[14];
    const float* gamma2 = (const float*)d_in[15];
    const float* beta2  = (const float*)d_in[16];
    float* out = (float*)d_out;

    float *p_h, *p_wqkv, *p_bqkv, *p_qkv, *p_attn, *p_x1, *p_h2, *p_ff;
    cudaGetSymbolAddress((void**)&p_h,    g_h);
    cudaGetSymbolAddress((void**)&p_wqkv, g_wqkv);
    cudaGetSymbolAddress((void**)&p_bqkv, g_bqkv);
    cudaGetSymbolAddress((void**)&p_qkv,  g_qkv);
    cudaGetSymbolAddress((void**)&p_attn, g_attn);
    cudaGetSymbolAddress((void**)&p_x1,   g_x1);
    cudaGetSymbolAddress((void**)&p_h2,   g_h2);
    cudaGetSymbolAddress((void**)&p_ff,   g_ff);

    cudaFuncSetAttribute(attn_tc_kernel,
                         cudaFuncAttributeMaxDynamicSharedMemorySize, ATTN_SMEM);

    // 0. pack qkv weights/biases
    pack_qkv_kernel<<<(HH*CC*HS + 255)/256, 256>>>(Wq, Wk, Wv, bq, bk, bv);

    // 1. LN1 (over sequence axis)
    ln_seq_kernel<<<dim3(CC/8, BB), dim3(8, 32)>>>(x, gamma1, beta1, p_h);

    // 2. QKV GEMM: [4096,1024] @ [1024,3072] + bias
    gemm_tc_kernel<1,0,0><<<dim3(3*CC/128, NROWS/128), 256>>>(
        p_h, p_wqkv, p_bqkv, nullptr, p_qkv, NROWS, 3*CC, CC);

    // 3. attention (tensor-core flash, no-max base-2 softmax)
    attn_tc_kernel<<<dim3(TT/128, HH, BB), 256, ATTN_SMEM>>>();

    // 4. output projection + residual: x1 = x + attn @ Wo + bo
    gemm_tc_kernel<1,0,1><<<dim3(CC/128, NROWS/128), 256>>>(
        p_attn, Wo, bo, x, p_x1, NROWS, CC, CC);

    // 5. LN2
    ln_seq_kernel<<<dim3(CC/8, BB), dim3(8, 32)>>>(p_x1, gamma2, beta2, p_h2);

    // 6. FF1 + relu: [4096,1024] @ [1024,4096]
    gemm_tc_kernel<1,1,0><<<dim3(4*CC/128, NROWS/128), 256>>>(
        p_h2, W1, b1, nullptr, p_ff, NROWS, 4*CC, CC);

    // 7. FF2 + residual -> out: [4096,4096] @ [4096,1024]
    gemm_tc_kernel<1,0,1><<<dim3(CC/128, NROWS/128), 256>>>(
        p_ff, W2, b2, p_x1, out, NROWS, CC, 4*CC);
}

// round 5
// speedup vs baseline: 3.3743x; 1.2655x over previous
#include <cuda_runtime.h>
#include <math.h>
#include <stdint.h>

// Problem constants
#define BB 2
#define TT 2048
#define CC 1024
#define HH 16
#define HS 64
#define NROWS (BB*TT)        // 4096
#define LN_EPS 1e-5f

// ---------------------------------------------------------------------------
// Scratch
// ---------------------------------------------------------------------------
__device__ float g_h   [NROWS*CC];
__device__ float g_wqkv[CC*3*CC];
__device__ float g_bqkv[3*CC];
__device__ float g_qkv [NROWS*3*CC];
__device__ float g_attn[NROWS*CC];
__device__ float g_x1  [NROWS*CC];
__device__ float g_h2  [NROWS*CC];
__device__ float g_ff  [NROWS*4*CC];

__device__ __forceinline__ float to_tf32(float x) {
    uint32_t u;
    asm("cvt.rna.tf32.f32 %0, %1;" : "=r"(u) : "f"(x));
    return __uint_as_float(u);
}
__device__ __forceinline__ float ex2_mufu(float y) {
    float r;
    asm("ex2.approx.ftz.f32 %0, %1;" : "=f"(r) : "f"(y));
    return r;
}
__device__ __forceinline__ float ex2_poly(float y) {
    float r = y + 12582912.f;
    int   n = __float_as_int(r);
    float t = r - 12582912.f;
    float f = y - t;
    float p = 0.00961813f;
    p = fmaf(p, f, 0.05550411f);
    p = fmaf(p, f, 0.24022651f);
    p = fmaf(p, f, 0.69314718f);
    p = fmaf(p, f, 1.0f);
    return __int_as_float(__float_as_int(p) + (n << 23));
}

// cp.async helpers
__device__ __forceinline__ void cp16(uint32_t dst, const void* src) {
    asm volatile("cp.async.cg.shared.global [%0], [%1], 16;\n"
                 :: "r"(dst), "l"(src));
}
#define CP_COMMIT() asm volatile("cp.async.commit_group;\n" ::: "memory")
#define CP_WAIT(n)  asm volatile("cp.async.wait_group %0;\n" :: "n"(n) : "memory")

// ---------------------------------------------------------------------------
// Pack Wq/Wk/Wv -> g_wqkv [C, 3C]
// ---------------------------------------------------------------------------
__global__ void pack_qkv_kernel(const float* __restrict__ Wq,
                                const float* __restrict__ Wk,
                                const float* __restrict__ Wv,
                                const float* __restrict__ bq,
                                const float* __restrict__ bk,
                                const float* __restrict__ bv) {
    int e = blockIdx.x * blockDim.x + threadIdx.x;
    if (e < HH*CC*HS) {
        int d = e % HS;
        int c = (e / HS) % CC;
        int h = e / (HS*CC);
        int col = h*HS + d;
        g_wqkv[(size_t)c*3*CC +        col] = Wq[e];
        g_wqkv[(size_t)c*3*CC + CC   + col] = Wk[e];
        g_wqkv[(size_t)c*3*CC + 2*CC + col] = Wv[e];
    }
    if (e < CC) {
        g_bqkv[e]        = bq[e];
        g_bqkv[CC + e]   = bk[e];
        g_bqkv[2*CC + e] = bv[e];
    }
}

// ---------------------------------------------------------------------------
// LayerNorm over sequence axis, coalesced: block (32 cols, 32 t-lanes)
// ---------------------------------------------------------------------------
__global__ void __launch_bounds__(1024)
ln_seq_kernel(const float* __restrict__ x,
              const float* __restrict__ gamma,
              const float* __restrict__ beta,
              float* __restrict__ out) {
    int b  = blockIdx.y;
    int tx = threadIdx.x, ty = threadIdx.y;
    int c  = blockIdx.x * 32 + tx;
    const float* xp = x   + (size_t)b*TT*CC + c;
    float*       op = out + (size_t)b*TT*CC + c;

    float s = 0.f, sq = 0.f;
    for (int t = ty; t < TT; t += 32) {
        float v = xp[(size_t)t*CC];
        s += v; sq += v*v;
    }
    __shared__ float ssum[32][33];
    __shared__ float ssq [32][33];
    ssum[ty][tx] = s; ssq[ty][tx] = sq;
    __syncthreads();
    for (int off = 16; off > 0; off >>= 1) {
        if (ty < off) {
            ssum[ty][tx] += ssum[ty+off][tx];
            ssq [ty][tx] += ssq [ty+off][tx];
        }
        __syncthreads();
    }
    __shared__ float meanv[32], rstdv[32];
    if (ty == 0) {
        float mean = ssum[0][tx] * (1.0f / TT);
        float var  = (ssq[0][tx] - (float)TT * mean * mean) * (1.0f / (TT - 1));
        meanv[tx]  = mean;
        rstdv[tx]  = 1.0f / (sqrtf(var) + LN_EPS);
    }
    __syncthreads();
    float mean = meanv[tx], rstd = rstdv[tx];
    float g = gamma[c], bt = beta[c];
    for (int t = ty; t < TT; t += 32) {
        float v = xp[(size_t)t*CC];
        op[(size_t)t*CC] = g * ((v - mean) * rstd) + bt;
    }
}

// ---------------------------------------------------------------------------
// TF32 tensor-core GEMM with cp.async double buffering.
// ---------------------------------------------------------------------------
#define MMA_TF32(d, a, b)                                                     \
    asm volatile(                                                             \
        "mma.sync.aligned.m16n8k8.row.col.f32.tf32.tf32.f32 "                 \
        "{%0,%1,%2,%3},{%4,%5,%6,%7},{%8,%9},{%0,%1,%2,%3};\n"                \
        : "+f"((d)[0]), "+f"((d)[1]), "+f"((d)[2]), "+f"((d)[3])              \
        : "r"((a)[0]), "r"((a)[1]), "r"((a)[2]), "r"((a)[3]),                 \
          "r"((b)[0]), "r"((b)[1]))

#define AS_FLOATS 4608    /* 128*36 */
#define BS_FLOATS 4352    /* 32*136 */
#define GEMM_SMEM ((2*AS_FLOATS + 2*BS_FLOATS)*4)

template<int DOBIAS, int DORELU, int DORES>
__global__ void __launch_bounds__(256, 2)
gemm_tc_kernel(const float* __restrict__ A, const float* __restrict__ Bm,
               const float* __restrict__ bias, const float* __restrict__ res,
               float* __restrict__ Cm, int M, int N, int K) {
    extern __shared__ float smg[];
    // layout: As0 | As1 | Bs0 | Bs1
    int tid  = threadIdx.x;
    int lane = tid & 31, wid = tid >> 5;
    int wm = (wid >> 1) * 32;
    int wn = (wid & 1) * 64;
    int g  = lane >> 2;
    int tg = lane & 3;
    int m0 = blockIdx.y * 128, n0 = blockIdx.x * 128;

    float acc[2][8][4];
#pragma unroll
    for (int mf = 0; mf < 2; mf++)
#pragma unroll
        for (int nf = 0; nf < 8; nf++)
#pragma unroll
            for (int r = 0; r < 4; r++) acc[mf][nf][r] = 0.f;

    int ar = tid >> 3, ac = (tid & 7) * 4;
    int br = tid >> 5, bc = (tid & 31) * 4;

    uint32_t smg_u = (uint32_t)__cvta_generic_to_shared(smg);
    int nk = K >> 5;

    // issue stage 0
    {
        uint32_t as_b = smg_u;
        uint32_t bs_b = smg_u + (2*AS_FLOATS)*4;
#pragma unroll
        for (int p = 0; p < 4; p++)
            cp16(as_b + ((ar + 32*p)*36 + ac)*4,
                 &A[(size_t)(m0 + ar + 32*p)*K + ac]);
#pragma unroll
        for (int p = 0; p < 4; p++)
            cp16(bs_b + ((br + 8*p)*136 + bc)*4,
                 &Bm[(size_t)(br + 8*p)*N + n0 + bc]);
        CP_COMMIT();
    }

    for (int i = 0; i < nk; i++) {
        int buf = i & 1;
        if (i + 1 < nk) {
            int k0 = (i + 1) << 5;
            int nb = (i + 1) & 1;
            uint32_t as_b = smg_u + (nb*AS_FLOATS)*4;
            uint32_t bs_b = smg_u + (2*AS_FLOATS + nb*BS_FLOATS)*4;
#pragma unroll
            for (int p = 0; p < 4; p++)
                cp16(as_b + ((ar + 32*p)*36 + ac)*4,
                     &A[(size_t)(m0 + ar + 32*p)*K + k0 + ac]);
#pragma unroll
            for (int p = 0; p < 4; p++)
                cp16(bs_b + ((br + 8*p)*136 + bc)*4,
                     &Bm[(size_t)(k0 + br + 8*p)*N + n0 + bc]);
            CP_COMMIT();
            CP_WAIT(1);
        } else {
            CP_WAIT(0);
        }
        __syncthreads();

        const float* As = smg + buf*AS_FLOATS;
        const float* Bs = smg + 2*AS_FLOATS + buf*BS_FLOATS;

#pragma unroll
        for (int ks = 0; ks < 4; ks++) {
            int kk = ks * 8;
            uint32_t afr[2][4];
#pragma unroll
            for (int mf = 0; mf < 2; mf++) {
                int r = wm + mf*16 + g;
                afr[mf][0] = __float_as_uint(As[(r    )*36 + kk + tg    ]);
                afr[mf][1] = __float_as_uint(As[(r + 8)*36 + kk + tg    ]);
                afr[mf][2] = __float_as_uint(As[(r    )*36 + kk + tg + 4]);
                afr[mf][3] = __float_as_uint(As[(r + 8)*36 + kk + tg + 4]);
            }
#pragma unroll
            for (int nf = 0; nf < 8; nf++) {
                uint32_t bfr[2];
                bfr[0] = __float_as_uint(Bs[(kk + tg    )*136 + wn + nf*8 + g]);
                bfr[1] = __float_as_uint(Bs[(kk + tg + 4)*136 + wn + nf*8 + g]);
#pragma unroll
                for (int mf = 0; mf < 2; mf++)
                    MMA_TF32(acc[mf][nf], afr[mf], bfr);
            }
        }
        __syncthreads();
    }

#pragma unroll
    for (int mf = 0; mf < 2; mf++) {
#pragma unroll
        for (int nf = 0; nf < 8; nf++) {
            int r  = m0 + wm + mf*16 + g;
            int cb = n0 + wn + nf*8 + 2*tg;
            float2 v0 = make_float2(acc[mf][nf][0], acc[mf][nf][1]);
            float2 v1 = make_float2(acc[mf][nf][2], acc[mf][nf][3]);
            if (DOBIAS) {
                float2 bsv = *(const float2*)&bias[cb];
                v0.x += bsv.x; v0.y += bsv.y;
                v1.x += bsv.x; v1.y += bsv.y;
            }
            if (DORELU) {
                v0.x = fmaxf(v0.x, 0.f); v0.y = fmaxf(v0.y, 0.f);
                v1.x = fmaxf(v1.x, 0.f); v1.y = fmaxf(v1.y, 0.f);
            }
            if (DORES) {
                float2 r0 = *(const float2*)&res[(size_t)r*N + cb];
                float2 r1 = *(const float2*)&res[(size_t)(r+8)*N + cb];
                v0.x += r0.x; v0.y += r0.y;
                v1.x += r1.x; v1.y += r1.y;
            }
            *(float2*)&Cm[(size_t)r*N + cb]     = v0;
            *(float2*)&Cm[(size_t)(r+8)*N + cb] = v1;
        }
    }
}

// ---------------------------------------------------------------------------
// Tensor-core flash attention, no-max base-2 softmax, register-resident P.
// q-tile 128 rows, kv-tile 64. 8 warps, warp owns 16 q-rows.
// S accum held in s[8][4]; exp'd in place; register-permuted to PV A-frags.
// smem: Qs[128][68] + Ks[64][68] + Vs[64][72]
// ---------------------------------------------------------------------------
#define QS_STRIDE 68
#define KS_STRIDE 68
#define VS_STRIDE 72
#define SM_QS 0
#define SM_KS (128*QS_STRIDE)
#define SM_VS (SM_KS + 64*KS_STRIDE)
#define ATTN_SMEM ((SM_VS + 64*VS_STRIDE)*4)
#define QSCALE 0.18033688f    /* 0.125 * log2(e) */

__global__ void __launch_bounds__(256, 2) attn_tc_kernel() {
    extern __shared__ float sm[];
    float* Qs = sm + SM_QS;
    float* Ks = sm + SM_KS;
    float* Vs = sm + SM_VS;

    int tid = threadIdx.x, lane = tid & 31, wid = tid >> 5;
    int g = lane >> 2, tg = lane & 3;
    int b = blockIdx.z, h = blockIdx.y;
    int tq0 = blockIdx.x * 128;
    int wr = wid * 16;

    const float* qbase = g_qkv + (size_t)b*TT*3*CC + (size_t)h*HS;
    const float* kbase = qbase + CC;
    const float* vbase = qbase + 2*CC;

    // load Q tile (pre-scaled, tf32)
#pragma unroll
    for (int p = 0; p < 8; p++) {
        int idx = tid + p*256;
        int r = idx >> 4, c4 = idx & 15;
        float4 v = *(const float4*)&qbase[(size_t)(tq0 + r)*3*CC + c4*4];
        v.x = to_tf32(v.x * QSCALE); v.y = to_tf32(v.y * QSCALE);
        v.z = to_tf32(v.z * QSCALE); v.w = to_tf32(v.w * QSCALE);
        *(float4*)&Qs[r*QS_STRIDE + c4*4] = v;
    }

    float o[8][4];
#pragma unroll
    for (int i = 0; i < 8; i++)
#pragma unroll
        for (int j = 0; j < 4; j++) o[i][j] = 0.f;
    float lsum0 = 0.f, lsum1 = 0.f;

    int srcA = (lane & ~3) + (tg >> 1);
    int srcB = srcA + 2;
    bool hi = (tg & 1);

    __syncthreads();

    for (int kt = 0; kt < TT; kt += 64) {
        // stage K and V tiles (tf32)
#pragma unroll
        for (int p = 0; p < 4; p++) {
            int idx = tid + p*256;
            int r = idx >> 4, c4 = idx & 15;
            float4 kv = *(const float4*)&kbase[(size_t)(kt + r)*3*CC + c4*4];
            kv.x = to_tf32(kv.x); kv.y = to_tf32(kv.y);
            kv.z = to_tf32(kv.z); kv.w = to_tf32(kv.w);
            *(float4*)&Ks[r*KS_STRIDE + c4*4] = kv;
            float4 vv = *(const float4*)&vbase[(size_t)(kt + r)*3*CC + c4*4];
            vv.x = to_tf32(vv.x); vv.y = to_tf32(vv.y);
            vv.z = to_tf32(vv.z); vv.w = to_tf32(vv.w);
            *(float4*)&Vs[r*VS_STRIDE + c4*4] = vv;
        }
        __syncthreads();

        // ---- S = Q K^T (log2 domain), 8 accumulators, Q frag loaded once/k8
        float s[8][4];
#pragma unroll
        for (int nf = 0; nf < 8; nf++)
#pragma unroll
            for (int j = 0; j < 4; j++) s[nf][j] = 0.f;

#pragma unroll
        for (int k8 = 0; k8 < 8; k8++) {
            int kk = k8 * 8;
            uint32_t aq[4];
            aq[0] = __float_as_uint(Qs[(wr+g  )*QS_STRIDE + kk + tg    ]);
            aq[1] = __float_as_uint(Qs[(wr+g+8)*QS_STRIDE + kk + tg    ]);
            aq[2] = __float_as_uint(Qs[(wr+g  )*QS_STRIDE + kk + tg + 4]);
            aq[3] = __float_as_uint(Qs[(wr+g+8)*QS_STRIDE + kk + tg + 4]);
#pragma unroll
            for (int nf = 0; nf < 8; nf++) {
                uint32_t bk[2];
                bk[0] = __float_as_uint(Ks[(nf*8+g)*KS_STRIDE + kk + tg    ]);
                bk[1] = __float_as_uint(Ks[(nf*8+g)*KS_STRIDE + kk + tg + 4]);
                MMA_TF32(s[nf], aq, bk);
            }
        }

        // ---- exp2 (dual pipe) + row-sum accumulation
#pragma unroll
        for (int nf = 0; nf < 8; nf++) {
            if (nf < 3) {
                s[nf][0] = ex2_mufu(fminf(s[nf][0], 80.f));
                s[nf][1] = ex2_mufu(fminf(s[nf][1], 80.f));
                s[nf][2] = ex2_mufu(fminf(s[nf][2], 80.f));
                s[nf][3] = ex2_mufu(fminf(s[nf][3], 80.f));
            } else {
                s[nf][0] = ex2_poly(fminf(fmaxf(s[nf][0], -80.f), 80.f));
                s[nf][1] = ex2_poly(fminf(fmaxf(s[nf][1], -80.f), 80.f));
                s[nf][2] = ex2_poly(fminf(fmaxf(s[nf][2], -80.f), 80.f));
                s[nf][3] = ex2_poly(fminf(fmaxf(s[nf][3], -80.f), 80.f));
            }
            lsum0 += s[nf][0] + s[nf][1];
            lsum1 += s[nf][2] + s[nf][3];
        }

        // ---- register permute: C-layout (cols 2tg,2tg+1) -> A-layout (tg,tg+4)
#pragma unroll
        for (int nf = 0; nf < 8; nf++) {
            float c0 = s[nf][0], c1 = s[nf][1], c2 = s[nf][2], c3 = s[nf][3];
            float u0 = __shfl_sync(0xffffffffu, c0, srcA);
            float u1 = __shfl_sync(0xffffffffu, c1, srcA);
            float u2 = __shfl_sync(0xffffffffu, c0, srcB);
            float u3 = __shfl_sync(0xffffffffu, c1, srcB);
            float w0 = __shfl_sync(0xffffffffu, c2, srcA);
            float w1 = __shfl_sync(0xffffffffu, c3, srcA);
            float w2 = __shfl_sync(0xffffffffu, c2, srcB);
            float w3 = __shfl_sync(0xffffffffu, c3, srcB);
            s[nf][0] = to_tf32(hi ? u1 : u0);   // row g,   k tg
            s[nf][1] = to_tf32(hi ? w1 : w0);   // row g+8, k tg
            s[nf][2] = to_tf32(hi ? u3 : u2);   // row g,   k tg+4
            s[nf][3] = to_tf32(hi ? w3 : w2);   // row g+8, k tg+4
        }

        // ---- O += P V  (P fragments register-resident: s[k8])
#pragma unroll
        for (int k8 = 0; k8 < 8; k8++) {
            int kk = k8 * 8;
            uint32_t ap[4];
            ap[0] = __float_as_uint(s[k8][0]);
            ap[1] = __float_as_uint(s[k8][1]);
            ap[2] = __float_as_uint(s[k8][2]);
            ap[3] = __float_as_uint(s[k8][3]);
#pragma unroll
            for (int nf = 0; nf < 8; nf++) {
                uint32_t bv[2];
                bv[0] = __float_as_uint(Vs[(kk+tg  )*VS_STRIDE + nf*8 + g]);
                bv[1] = __float_as_uint(Vs[(kk+tg+4)*VS_STRIDE + nf*8 + g]);
                MMA_TF32(o[nf], ap, bv);
            }
        }
        __syncthreads();
    }

    // row-sum reduce across the 4-lane group
    lsum0 += __shfl_xor_sync(0xffffffffu, lsum0, 1);
    lsum0 += __shfl_xor_sync(0xffffffffu, lsum0, 2);
    lsum1 += __shfl_xor_sync(0xffffffffu, lsum1, 1);
    lsum1 += __shfl_xor_sync(0xffffffffu, lsum1, 2);
    float inv0 = 1.0f / lsum0, inv1 = 1.0f / lsum1;

    int row0 = b*TT + tq0 + wr + g;
#pragma unroll
    for (int nf = 0; nf < 8; nf++) {
        int col = h*HS + nf*8 + 2*tg;
        float2 v0 = make_float2(o[nf][0]*inv0, o[nf][1]*inv0);
        float2 v1 = make_float2(o[nf][2]*inv1, o[nf][3]*inv1);
        *(float2*)&g_attn[(size_t)row0*CC + col]     = v0;
        *(float2*)&g_attn[(size_t)(row0+8)*CC + col] = v1;
    }
}

// ---------------------------------------------------------------------------
// Launch
// ---------------------------------------------------------------------------
extern "C" void kernel_launch(void* const* d_in, const int* in_sizes, int n_in,
                              void* d_out, int out_size) {
    const float* x      = (const float*)d_in[0];
    const float* Wq     = (const float*)d_in[1];
    const float* bq     = (const float*)d_in[2];
    const float* Wk     = (const float*)d_in[3];
    const float* bk     = (const float*)d_in[4];
    const float* Wv     = (const float*)d_in[5];
    const float* bv     = (const float*)d_in[6];
    const float* Wo     = (const float*)d_in[7];
    const float* bo     = (const float*)d_in[8];
    const float* W1     = (const float*)d_in[9];
    const float* b1     = (const float*)d_in[10];
    const float* W2     = (const float*)d_in[11];
    const float* b2     = (const float*)d_in[12];
    const float* gamma1 = (const float*)d_in[13];
    const float* beta1  = (const float*)d_in[14];
    const float* gamma2 = (const float*)d_in[15];
    const float* beta2  = (const float*)d_in[16];
    float* out = (float*)d_out;

    float *p_h, *p_wqkv, *p_bqkv, *p_qkv, *p_attn, *p_x1, *p_h2, *p_ff;
    cudaGetSymbolAddress((void**)&p_h,    g_h);
    cudaGetSymbolAddress((void**)&p_wqkv, g_wqkv);
    cudaGetSymbolAddress((void**)&p_bqkv, g_bqkv);
    cudaGetSymbolAddress((void**)&p_qkv,  g_qkv);
    cudaGetSymbolAddress((void**)&p_attn, g_attn);
    cudaGetSymbolAddress((void**)&p_x1,   g_x1);
    cudaGetSymbolAddress((void**)&p_h2,   g_h2);
    cudaGetSymbolAddress((void**)&p_ff,   g_ff);

    cudaFuncSetAttribute(attn_tc_kernel,
                         cudaFuncAttributeMaxDynamicSharedMemorySize, ATTN_SMEM);
    cudaFuncSetAttribute(gemm_tc_kernel<1,0,0>,
                         cudaFuncAttributeMaxDynamicSharedMemorySize, GEMM_SMEM);
    cudaFuncSetAttribute(gemm_tc_kernel<1,0,1>,
                         cudaFuncAttributeMaxDynamicSharedMemorySize, GEMM_SMEM);
    cudaFuncSetAttribute(gemm_tc_kernel<1,1,0>,
                         cudaFuncAttributeMaxDynamicSharedMemorySize, GEMM_SMEM);

    // 0. pack qkv weights/biases
    pack_qkv_kernel<<<(HH*CC*HS + 255)/256, 256>>>(Wq, Wk, Wv, bq, bk, bv);

    // 1. LN1
    ln_seq_kernel<<<dim3(CC/32, BB), dim3(32, 32)>>>(x, gamma1, beta1, p_h);

    // 2. QKV GEMM
    gemm_tc_kernel<1,0,0><<<dim3(3*CC/128, NROWS/128), 256, GEMM_SMEM>>>(
        p_h, p_wqkv, p_bqkv, nullptr, p_qkv, NROWS, 3*CC, CC);

    // 3. attention
    attn_tc_kernel<<<dim3(TT/128, HH, BB), 256, ATTN_SMEM>>>();

    // 4. output projection + residual
    gemm_tc_kernel<1,0,1><<<dim3(CC/128, NROWS/128), 256, GEMM_SMEM>>>(
        p_attn, Wo, bo, x, p_x1, NROWS, CC, CC);

    // 5. LN2
    ln_seq_kernel<<<dim3(CC/32, BB), dim3(32, 32)>>>(p_x1, gamma2, beta2, p_h2);

    // 6. FF1 + relu
    gemm_tc_kernel<1,1,0><<<dim3(4*CC/128, NROWS/128), 256, GEMM_SMEM>>>(
        p_h2, W1, b1, nullptr, p_ff, NROWS, 4*CC, CC);

    // 7. FF2 + residual -> out
    gemm_tc_kernel<1,0,1><<<dim3(CC/128, NROWS/128), 256, GEMM_SMEM>>>(
        p_ff, W2, b2, p_x1, out, NROWS, CC, 4*CC);
}

// round 6
// speedup vs baseline: 3.6216x; 1.0733x over previous
#include <cuda_runtime.h>
#include <math.h>
#include <stdint.h>

// Problem constants
#define BB 2
#define TT 2048
#define CC 1024
#define HH 16
#define HS 64
#define NROWS (BB*TT)        // 4096
#define LN_EPS 1e-5f

// ---------------------------------------------------------------------------
// Scratch
// ---------------------------------------------------------------------------
__device__ float g_h   [NROWS*CC];
__device__ float g_wqkv[CC*3*CC];
__device__ float g_bqkv[3*CC];
__device__ float g_qkv [NROWS*3*CC];
__device__ float g_attn[NROWS*CC];
__device__ float g_x1  [NROWS*CC];
__device__ float g_h2  [NROWS*CC];
__device__ float g_ff  [NROWS*4*CC];
__device__ float g_wor [CC*CC];        // tf32-rounded Wo
__device__ float g_w1r [CC*4*CC];      // tf32-rounded W1
__device__ float g_w2r [4*CC*CC];      // tf32-rounded W2

__device__ __forceinline__ float to_tf32(float x) {
    uint32_t u;
    asm("cvt.rna.tf32.f32 %0, %1;" : "=r"(u) : "f"(x));
    return __uint_as_float(u);
}
__device__ __forceinline__ float ex2_mufu(float y) {
    float r;
    asm("ex2.approx.ftz.f32 %0, %1;" : "=f"(r) : "f"(y));
    return r;
}
__device__ __forceinline__ float ex2_poly(float y) {
    float r = y + 12582912.f;
    int   n = __float_as_int(r);
    float t = r - 12582912.f;
    float f = y - t;
    float p = 0.00961813f;
    p = fmaf(p, f, 0.05550411f);
    p = fmaf(p, f, 0.24022651f);
    p = fmaf(p, f, 0.69314718f);
    p = fmaf(p, f, 1.0f);
    return __int_as_float(__float_as_int(p) + (n << 23));
}
// pack two floats into bf16x2 (lo = first arg)
__device__ __forceinline__ uint32_t pack_bf16x2(float lo, float hi) {
    uint32_t r;
    asm("cvt.rn.bf16x2.f32 %0, %1, %2;" : "=r"(r) : "f"(hi), "f"(lo));
    return r;
}

// cp.async helpers
__device__ __forceinline__ void cp16(uint32_t dst, const void* src) {
    asm volatile("cp.async.cg.shared.global [%0], [%1], 16;\n"
                 :: "r"(dst), "l"(src));
}
#define CP_COMMIT() asm volatile("cp.async.commit_group;\n" ::: "memory")
#define CP_WAIT(n)  asm volatile("cp.async.wait_group %0;\n" :: "n"(n) : "memory")

// ---------------------------------------------------------------------------
// Pack Wq/Wk/Wv -> g_wqkv [C, 3C]  (tf32-rounded)
// ---------------------------------------------------------------------------
__global__ void pack_qkv_kernel(const float* __restrict__ Wq,
                                const float* __restrict__ Wk,
                                const float* __restrict__ Wv,
                                const float* __restrict__ bq,
                                const float* __restrict__ bk,
                                const float* __restrict__ bv) {
    int e = blockIdx.x * blockDim.x + threadIdx.x;
    if (e < HH*CC*HS) {
        int d = e % HS;
        int c = (e / HS) % CC;
        int h = e / (HS*CC);
        int col = h*HS + d;
        g_wqkv[(size_t)c*3*CC +        col] = to_tf32(Wq[e]);
        g_wqkv[(size_t)c*3*CC + CC   + col] = to_tf32(Wk[e]);
        g_wqkv[(size_t)c*3*CC + 2*CC + col] = to_tf32(Wv[e]);
    }
    if (e < CC) {
        g_bqkv[e]        = bq[e];
        g_bqkv[CC + e]   = bk[e];
        g_bqkv[2*CC + e] = bv[e];
    }
}

// ---------------------------------------------------------------------------
// Round Wo / W1 / W2 to tf32 (one-time copy into scratch)
// ---------------------------------------------------------------------------
__global__ void round_w_kernel(const float* __restrict__ Wo,
                               const float* __restrict__ W1,
                               const float* __restrict__ W2) {
    int i4 = blockIdx.x * blockDim.x + threadIdx.x;   // float4 index
    const int NWO = CC*CC/4, NW1 = CC*4*CC/4, NW2 = 4*CC*CC/4;
    if (i4 < NWO) {
        float4 v = *(const float4*)&Wo[i4*4];
        v.x = to_tf32(v.x); v.y = to_tf32(v.y);
        v.z = to_tf32(v.z); v.w = to_tf32(v.w);
        *(float4*)&g_wor[i4*4] = v;
    } else if (i4 < NWO + NW1) {
        int j = i4 - NWO;
        float4 v = *(const float4*)&W1[(size_t)j*4];
        v.x = to_tf32(v.x); v.y = to_tf32(v.y);
        v.z = to_tf32(v.z); v.w = to_tf32(v.w);
        *(float4*)&g_w1r[(size_t)j*4] = v;
    } else if (i4 < NWO + NW1 + NW2) {
        int j = i4 - NWO - NW1;
        float4 v = *(const float4*)&W2[(size_t)j*4];
        v.x = to_tf32(v.x); v.y = to_tf32(v.y);
        v.z = to_tf32(v.z); v.w = to_tf32(v.w);
        *(float4*)&g_w2r[(size_t)j*4] = v;
    }
}

// ---------------------------------------------------------------------------
// LayerNorm over sequence axis, coalesced; output tf32-rounded (feeds GEMM A)
// ---------------------------------------------------------------------------
__global__ void __launch_bounds__(1024)
ln_seq_kernel(const float* __restrict__ x,
              const float* __restrict__ gamma,
              const float* __restrict__ beta,
              float* __restrict__ out) {
    int b  = blockIdx.y;
    int tx = threadIdx.x, ty = threadIdx.y;
    int c  = blockIdx.x * 32 + tx;
    const float* xp = x   + (size_t)b*TT*CC + c;
    float*       op = out + (size_t)b*TT*CC + c;

    float s = 0.f, sq = 0.f;
    for (int t = ty; t < TT; t += 32) {
        float v = xp[(size_t)t*CC];
        s += v; sq += v*v;
    }
    __shared__ float ssum[32][33];
    __shared__ float ssq [32][33];
    ssum[ty][tx] = s; ssq[ty][tx] = sq;
    __syncthreads();
    for (int off = 16; off > 0; off >>= 1) {
        if (ty < off) {
            ssum[ty][tx] += ssum[ty+off][tx];
            ssq [ty][tx] += ssq [ty+off][tx];
        }
        __syncthreads();
    }
    __shared__ float meanv[32], rstdv[32];
    if (ty == 0) {
        float mean = ssum[0][tx] * (1.0f / TT);
        float var  = (ssq[0][tx] - (float)TT * mean * mean) * (1.0f / (TT - 1));
        meanv[tx]  = mean;
        rstdv[tx]  = 1.0f / (sqrtf(var) + LN_EPS);
    }
    __syncthreads();
    float mean = meanv[tx], rstd = rstdv[tx];
    float g = gamma[c], bt = beta[c];
    for (int t = ty; t < TT; t += 32) {
        float v = xp[(size_t)t*CC];
        op[(size_t)t*CC] = to_tf32(g * ((v - mean) * rstd) + bt);
    }
}

// ---------------------------------------------------------------------------
// TF32 tensor-core GEMM with cp.async double buffering.
// Inputs are pre-rounded to tf32 (producers/weight copies), so HW truncation
// in the mma is exact.  DOROUND rounds the OUTPUT (when it feeds another GEMM).
// ---------------------------------------------------------------------------
#define MMA_TF32(d, a, b)                                                     \
    asm volatile(                                                             \
        "mma.sync.aligned.m16n8k8.row.col.f32.tf32.tf32.f32 "                 \
        "{%0,%1,%2,%3},{%4,%5,%6,%7},{%8,%9},{%0,%1,%2,%3};\n"                \
        : "+f"((d)[0]), "+f"((d)[1]), "+f"((d)[2]), "+f"((d)[3])              \
        : "r"((a)[0]), "r"((a)[1]), "r"((a)[2]), "r"((a)[3]),                 \
          "r"((b)[0]), "r"((b)[1]))

#define AS_FLOATS 4608    /* 128*36 */
#define BS_FLOATS 4352    /* 32*136 */
#define GEMM_SMEM ((2*AS_FLOATS + 2*BS_FLOATS)*4)

template<int DOBIAS, int DORELU, int DORES, int DOROUND>
__global__ void __launch_bounds__(256, 2)
gemm_tc_kernel(const float* __restrict__ A, const float* __restrict__ Bm,
               const float* __restrict__ bias, const float* __restrict__ res,
               float* __restrict__ Cm, int M, int N, int K) {
    extern __shared__ float smg[];
    int tid  = threadIdx.x;
    int lane = tid & 31, wid = tid >> 5;
    int wm = (wid >> 1) * 32;
    int wn = (wid & 1) * 64;
    int g  = lane >> 2;
    int tg = lane & 3;
    int m0 = blockIdx.y * 128, n0 = blockIdx.x * 128;

    float acc[2][8][4];
#pragma unroll
    for (int mf = 0; mf < 2; mf++)
#pragma unroll
        for (int nf = 0; nf < 8; nf++)
#pragma unroll
            for (int r = 0; r < 4; r++) acc[mf][nf][r] = 0.f;

    int ar = tid >> 3, ac = (tid & 7) * 4;
    int br = tid >> 5, bc = (tid & 31) * 4;

    uint32_t smg_u = (uint32_t)__cvta_generic_to_shared(smg);
    int nk = K >> 5;

    {
        uint32_t as_b = smg_u;
        uint32_t bs_b = smg_u + (2*AS_FLOATS)*4;
#pragma unroll
        for (int p = 0; p < 4; p++)
            cp16(as_b + ((ar + 32*p)*36 + ac)*4,
                 &A[(size_t)(m0 + ar + 32*p)*K + ac]);
#pragma unroll
        for (int p = 0; p < 4; p++)
            cp16(bs_b + ((br + 8*p)*136 + bc)*4,
                 &Bm[(size_t)(br + 8*p)*N + n0 + bc]);
        CP_COMMIT();
    }

    for (int i = 0; i < nk; i++) {
        int buf = i & 1;
        if (i + 1 < nk) {
            int k0 = (i + 1) << 5;
            int nb = (i + 1) & 1;
            uint32_t as_b = smg_u + (nb*AS_FLOATS)*4;
            uint32_t bs_b = smg_u + (2*AS_FLOATS + nb*BS_FLOATS)*4;
#pragma unroll
            for (int p = 0; p < 4; p++)
                cp16(as_b + ((ar + 32*p)*36 + ac)*4,
                     &A[(size_t)(m0 + ar + 32*p)*K + k0 + ac]);
#pragma unroll
            for (int p = 0; p < 4; p++)
                cp16(bs_b + ((br + 8*p)*136 + bc)*4,
                     &Bm[(size_t)(k0 + br + 8*p)*N + n0 + bc]);
            CP_COMMIT();
            CP_WAIT(1);
        } else {
            CP_WAIT(0);
        }
        __syncthreads();

        const float* As = smg + buf*AS_FLOATS;
        const float* Bs = smg + 2*AS_FLOATS + buf*BS_FLOATS;

#pragma unroll
        for (int ks = 0; ks < 4; ks++) {
            int kk = ks * 8;
            uint32_t afr[2][4];
#pragma unroll
            for (int mf = 0; mf < 2; mf++) {
                int r = wm + mf*16 + g;
                afr[mf][0] = __float_as_uint(As[(r    )*36 + kk + tg    ]);
                afr[mf][1] = __float_as_uint(As[(r + 8)*36 + kk + tg    ]);
                afr[mf][2] = __float_as_uint(As[(r    )*36 + kk + tg + 4]);
                afr[mf][3] = __float_as_uint(As[(r + 8)*36 + kk + tg + 4]);
            }
#pragma unroll
            for (int nf = 0; nf < 8; nf++) {
                uint32_t bfr[2];
                bfr[0] = __float_as_uint(Bs[(kk + tg    )*136 + wn + nf*8 + g]);
                bfr[1] = __float_as_uint(Bs[(kk + tg + 4)*136 + wn + nf*8 + g]);
#pragma unroll
                for (int mf = 0; mf < 2; mf++)
                    MMA_TF32(acc[mf][nf], afr[mf], bfr);
            }
        }
        __syncthreads();
    }

#pragma unroll
    for (int mf = 0; mf < 2; mf++) {
#pragma unroll
        for (int nf = 0; nf < 8; nf++) {
            int r  = m0 + wm + mf*16 + g;
            int cb = n0 + wn + nf*8 + 2*tg;
            float2 v0 = make_float2(acc[mf][nf][0], acc[mf][nf][1]);
            float2 v1 = make_float2(acc[mf][nf][2], acc[mf][nf][3]);
            if (DOBIAS) {
                float2 bsv = *(const float2*)&bias[cb];
                v0.x += bsv.x; v0.y += bsv.y;
                v1.x += bsv.x; v1.y += bsv.y;
            }
            if (DORELU) {
                v0.x = fmaxf(v0.x, 0.f); v0.y = fmaxf(v0.y, 0.f);
                v1.x = fmaxf(v1.x, 0.f); v1.y = fmaxf(v1.y, 0.f);
            }
            if (DORES) {
                float2 r0 = *(const float2*)&res[(size_t)r*N + cb];
                float2 r1 = *(const float2*)&res[(size_t)(r+8)*N + cb];
                v0.x += r0.x; v0.y += r0.y;
                v1.x += r1.x; v1.y += r1.y;
            }
            if (DOROUND) {
                v0.x = to_tf32(v0.x); v0.y = to_tf32(v0.y);
                v1.x = to_tf32(v1.x); v1.y = to_tf32(v1.y);
            }
            *(float2*)&Cm[(size_t)r*N + cb]     = v0;
            *(float2*)&Cm[(size_t)(r+8)*N + cb] = v1;
        }
    }
}

// ---------------------------------------------------------------------------
// bf16 tensor-core flash attention, no-max base-2 softmax.
// m16n8k16 bf16 mma; S C-frag col-pairs pack directly into PV A-frags
// (FA2 layout trick, zero shuffles).  V staged transposed (s-pairs packed).
// smem (uint32): Qs[128][36] + Ks[64][36] + Vt[64][36] = 36 KB
// ---------------------------------------------------------------------------
#define QS32 36
#define KS32 36
#define VS32 36
#define SM32_QS 0
#define SM32_KS (128*QS32)
#define SM32_VT (SM32_KS + 64*KS32)
#define ATTN_SMEM ((SM32_VT + 64*VS32)*4)
#define QSCALE 0.18033688f    /* 0.125 * log2(e) */

#define MMA_BF16(d, a, b)                                                     \
    asm volatile(                                                             \
        "mma.sync.aligned.m16n8k16.row.col.f32.bf16.bf16.f32 "                \
        "{%0,%1,%2,%3},{%4,%5,%6,%7},{%8,%9},{%0,%1,%2,%3};\n"                \
        : "+f"((d)[0]), "+f"((d)[1]), "+f"((d)[2]), "+f"((d)[3])              \
        : "r"((a)[0]), "r"((a)[1]), "r"((a)[2]), "r"((a)[3]),                 \
          "r"((b)[0]), "r"((b)[1]))

__global__ void __launch_bounds__(256, 2) attn_tc_kernel() {
    extern __shared__ uint32_t smu[];
    uint32_t* Qs = smu + SM32_QS;   // [row][dim-pair], stride 36
    uint32_t* Ks = smu + SM32_KS;   // [key][dim-pair], stride 36
    uint32_t* Vt = smu + SM32_VT;   // [dim][s-pair],   stride 36

    int tid = threadIdx.x, lane = tid & 31, wid = tid >> 5;
    int g = lane >> 2, tg = lane & 3;
    int b = blockIdx.z, h = blockIdx.y;
    int tq0 = blockIdx.x * 128;
    int wr = wid * 16;

    const float* qbase = g_qkv + (size_t)b*TT*3*CC + (size_t)h*HS;
    const float* kbase = qbase + CC;
    const float* vbase = qbase + 2*CC;

    // stage Q (pre-scaled, bf16 pairs)
#pragma unroll
    for (int p = 0; p < 8; p++) {
        int idx = tid + p*256;
        int r = idx >> 4, c4 = idx & 15;
        float4 v = *(const float4*)&qbase[(size_t)(tq0 + r)*3*CC + c4*4];
        Qs[r*QS32 + c4*2    ] = pack_bf16x2(v.x*QSCALE, v.y*QSCALE);
        Qs[r*QS32 + c4*2 + 1] = pack_bf16x2(v.z*QSCALE, v.w*QSCALE);
    }

    float o[8][4];
#pragma unroll
    for (int i = 0; i < 8; i++)
#pragma unroll
        for (int j = 0; j < 4; j++) o[i][j] = 0.f;
    float lsum0 = 0.f, lsum1 = 0.f;

    __syncthreads();

    for (int kt = 0; kt < TT; kt += 64) {
        // stage K (key-major bf16 pairs)
#pragma unroll
        for (int p = 0; p < 4; p++) {
            int idx = tid + p*256;
            int r = idx >> 4, c4 = idx & 15;
            float4 v = *(const float4*)&kbase[(size_t)(kt + r)*3*CC + c4*4];
            Ks[r*KS32 + c4*2    ] = pack_bf16x2(v.x, v.y);
            Ks[r*KS32 + c4*2 + 1] = pack_bf16x2(v.z, v.w);
        }
        // stage V transposed: Vt[dim][s-pair]
#pragma unroll
        for (int p = 0; p < 2; p++) {
            int idx = tid + p*256;          // 512 items: 32 s-pairs x 16 d-groups
            int sp = idx & 31, dg = idx >> 5;
            int d0 = dg * 4;
            float4 v0 = *(const float4*)&vbase[(size_t)(kt + 2*sp    )*3*CC + d0];
            float4 v1 = *(const float4*)&vbase[(size_t)(kt + 2*sp + 1)*3*CC + d0];
            Vt[(d0    )*VS32 + sp] = pack_bf16x2(v0.x, v1.x);
            Vt[(d0 + 1)*VS32 + sp] = pack_bf16x2(v0.y, v1.y);
            Vt[(d0 + 2)*VS32 + sp] = pack_bf16x2(v0.z, v1.z);
            Vt[(d0 + 3)*VS32 + sp] = pack_bf16x2(v0.w, v1.w);
        }
        __syncthreads();

        // ---- S = Q K^T (log2 domain), 4 k16 chunks
        float s[8][4];
#pragma unroll
        for (int nf = 0; nf < 8; nf++)
#pragma unroll
            for (int j = 0; j < 4; j++) s[nf][j] = 0.f;

#pragma unroll
        for (int c = 0; c < 4; c++) {
            int c8 = c * 8;
            uint32_t aq[4];
            aq[0] = Qs[(wr+g  )*QS32 + c8 + tg    ];
            aq[1] = Qs[(wr+g+8)*QS32 + c8 + tg    ];
            aq[2] = Qs[(wr+g  )*QS32 + c8 + tg + 4];
            aq[3] = Qs[(wr+g+8)*QS32 + c8 + tg + 4];
#pragma unroll
            for (int nf = 0; nf < 8; nf++) {
                uint32_t bk[2];
                bk[0] = Ks[(nf*8+g)*KS32 + c8 + tg    ];
                bk[1] = Ks[(nf*8+g)*KS32 + c8 + tg + 4];
                MMA_BF16(s[nf], aq, bk);
            }
        }

        // ---- exp2 (dual pipe) + row sums
#pragma unroll
        for (int nf = 0; nf < 8; nf++) {
            if (nf < 4) {
                s[nf][0] = ex2_mufu(fminf(s[nf][0], 80.f));
                s[nf][1] = ex2_mufu(fminf(s[nf][1], 80.f));
                s[nf][2] = ex2_mufu(fminf(s[nf][2], 80.f));
                s[nf][3] = ex2_mufu(fminf(s[nf][3], 80.f));
            } else {
                s[nf][0] = ex2_poly(fminf(fmaxf(s[nf][0], -80.f), 80.f));
                s[nf][1] = ex2_poly(fminf(fmaxf(s[nf][1], -80.f), 80.f));
                s[nf][2] = ex2_poly(fminf(fmaxf(s[nf][2], -80.f), 80.f));
                s[nf][3] = ex2_poly(fminf(fmaxf(s[nf][3], -80.f), 80.f));
            }
            lsum0 += s[nf][0] + s[nf][1];
            lsum1 += s[nf][2] + s[nf][3];
        }

        // ---- O += P V : C-frag pairs pack straight into bf16 A-frags
#pragma unroll
        for (int j = 0; j < 4; j++) {
            uint32_t ap[4];
            ap[0] = pack_bf16x2(s[2*j  ][0], s[2*j  ][1]);   // row g,   k 16j+2tg
            ap[1] = pack_bf16x2(s[2*j  ][2], s[2*j  ][3]);   // row g+8
            ap[2] = pack_bf16x2(s[2*j+1][0], s[2*j+1][1]);   // row g,   k 16j+8+2tg
            ap[3] = pack_bf16x2(s[2*j+1][2], s[2*j+1][3]);   // row g+8
            int c8 = j * 8;
#pragma unroll
            for (int nf = 0; nf < 8; nf++) {
                uint32_t bv[2];
                bv[0] = Vt[(nf*8+g)*VS32 + c8 + tg    ];
                bv[1] = Vt[(nf*8+g)*VS32 + c8 + tg + 4];
                MMA_BF16(o[nf], ap, bv);
            }
        }
        __syncthreads();
    }

    // row-sum reduce across the 4-lane group
    lsum0 += __shfl_xor_sync(0xffffffffu, lsum0, 1);
    lsum0 += __shfl_xor_sync(0xffffffffu, lsum0, 2);
    lsum1 += __shfl_xor_sync(0xffffffffu, lsum1, 1);
    lsum1 += __shfl_xor_sync(0xffffffffu, lsum1, 2);
    float inv0 = 1.0f / lsum0, inv1 = 1.0f / lsum1;

    int row0 = b*TT + tq0 + wr + g;
#pragma unroll
    for (int nf = 0; nf < 8; nf++) {
        int col = h*HS + nf*8 + 2*tg;
        float2 v0 = make_float2(to_tf32(o[nf][0]*inv0), to_tf32(o[nf][1]*inv0));
        float2 v1 = make_float2(to_tf32(o[nf][2]*inv1), to_tf32(o[nf][3]*inv1));
        *(float2*)&g_attn[(size_t)row0*CC + col]     = v0;
        *(float2*)&g_attn[(size_t)(row0+8)*CC + col] = v1;
    }
}

// ---------------------------------------------------------------------------
// Launch
// ---------------------------------------------------------------------------
extern "C" void kernel_launch(void* const* d_in, const int* in_sizes, int n_in,
                              void* d_out, int out_size) {
    const float* x      = (const float*)d_in[0];
    const float* Wq     = (const float*)d_in[1];
    const float* bq     = (const float*)d_in[2];
    const float* Wk     = (const float*)d_in[3];
    const float* bk     = (const float*)d_in[4];
    const float* Wv     = (const float*)d_in[5];
    const float* bv     = (const float*)d_in[6];
    const float* Wo     = (const float*)d_in[7];
    const float* bo     = (const float*)d_in[8];
    const float* W1     = (const float*)d_in[9];
    const float* b1     = (const float*)d_in[10];
    const float* W2     = (const float*)d_in[11];
    const float* b2     = (const float*)d_in[12];
    const float* gamma1 = (const float*)d_in[13];
    const float* beta1  = (const float*)d_in[14];
    const float* gamma2 = (const float*)d_in[15];
    const float* beta2  = (const float*)d_in[16];
    float* out = (float*)d_out;

    float *p_h, *p_wqkv, *p_bqkv, *p_qkv, *p_attn, *p_x1, *p_h2, *p_ff;
    float *p_wor, *p_w1r, *p_w2r;
    cudaGetSymbolAddress((void**)&p_h,    g_h);
    cudaGetSymbolAddress((void**)&p_wqkv, g_wqkv);
    cudaGetSymbolAddress((void**)&p_bqkv, g_bqkv);
    cudaGetSymbolAddress((void**)&p_qkv,  g_qkv);
    cudaGetSymbolAddress((void**)&p_attn, g_attn);
    cudaGetSymbolAddress((void**)&p_x1,   g_x1);
    cudaGetSymbolAddress((void**)&p_h2,   g_h2);
    cudaGetSymbolAddress((void**)&p_ff,   g_ff);
    cudaGetSymbolAddress((void**)&p_wor,  g_wor);
    cudaGetSymbolAddress((void**)&p_w1r,  g_w1r);
    cudaGetSymbolAddress((void**)&p_w2r,  g_w2r);

    cudaFuncSetAttribute(attn_tc_kernel,
                         cudaFuncAttributeMaxDynamicSharedMemorySize, ATTN_SMEM);
    cudaFuncSetAttribute(gemm_tc_kernel<1,0,0,0>,
                         cudaFuncAttributeMaxDynamicSharedMemorySize, GEMM_SMEM);
    cudaFuncSetAttribute(gemm_tc_kernel<1,0,1,0>,
                         cudaFuncAttributeMaxDynamicSharedMemorySize, GEMM_SMEM);
    cudaFuncSetAttribute(gemm_tc_kernel<1,1,0,1>,
                         cudaFuncAttributeMaxDynamicSharedMemorySize, GEMM_SMEM);

    // 0. pack qkv weights (tf32) + round big weights (tf32)
    pack_qkv_kernel<<<(HH*CC*HS + 255)/256, 256>>>(Wq, Wk, Wv, bq, bk, bv);
    round_w_kernel<<<(9*CC*CC/4 + 255)/256, 256>>>(Wo, W1, W2);

    // 1. LN1 (tf32-rounded output)
    ln_seq_kernel<<<dim3(CC/32, BB), dim3(32, 32)>>>(x, gamma1, beta1, p_h);

    // 2. QKV GEMM
    gemm_tc_kernel<1,0,0,0><<<dim3(3*CC/128, NROWS/128), 256, GEMM_SMEM>>>(
        p_h, p_wqkv, p_bqkv, nullptr, p_qkv, NROWS, 3*CC, CC);

    // 3. attention (bf16 tensor-core flash)
    attn_tc_kernel<<<dim3(TT/128, HH, BB), 256, ATTN_SMEM>>>();

    // 4. output projection + residual (A=g_attn already tf32-rounded)
    gemm_tc_kernel<1,0,1,0><<<dim3(CC/128, NROWS/128), 256, GEMM_SMEM>>>(
        p_attn, p_wor, bo, x, p_x1, NROWS, CC, CC);

    // 5. LN2 (tf32-rounded output)
    ln_seq_kernel<<<dim3(CC/32, BB), dim3(32, 32)>>>(p_x1, gamma2, beta2, p_h2);

    // 6. FF1 + relu (round output: feeds FF2)
    gemm_tc_kernel<1,1,0,1><<<dim3(4*CC/128, NROWS/128), 256, GEMM_SMEM>>>(
        p_h2, p_w1r, b1, nullptr, p_ff, NROWS, 4*CC, CC);

    // 7. FF2 + residual -> out (no rounding on final output)
    gemm_tc_kernel<1,0,1,0><<<dim3(CC/128, NROWS/128), 256, GEMM_SMEM>>>(
        p_ff, p_w2r, b2, p_x1, out, NROWS, CC, 4*CC);
}